// round 12
// baseline (speedup 1.0000x reference)
#include <cuda_runtime.h>
#include <cstdint>

#define TOKENS 4096
#define DMODEL 1024
#define NEXP   8
#define TOPK   2
#define HID    4096
#define CAP    1024

// ---- gemm geometry: 256x128 CTA tile, BK=32, 8 warps of 64x64 ----
#define BM 256
#define BN 128
#define AS_LD   36
#define BS_LDN  36
#define AS_SZF  (BM * AS_LD)            // 9216 floats
#define BS_SZF  (BN * BS_LDN)           // 4608 floats
#define STAGE_F (AS_SZF + BS_SZF)       // 13824 floats
#define STAGE_B (STAGE_F * 4)           // 55296 bytes
#define NSTAGE  3
#define SMEM_BYTES (NSTAGE * STAGE_B)   // 165888 bytes

// ---------------- device scratch (no allocations allowed) ----------------
__device__ int   g_idx[TOKENS * TOPK];
__device__ float g_gate[TOKENS * TOPK];
__device__ int   g_slot_tok[NEXP * CAP];
__device__ float g_slot_w[NEXP * CAP];
__device__ float g_h[(size_t)NEXP * CAP * HID];            // hidden (tf32-rounded)
__device__ float g_xt[(size_t)TOKENS * DMODEL];            // x (tf32-rounded)
__device__ float g_w1t[(size_t)NEXP * HID * DMODEL];       // w1^T [e][h][d] tf32
__device__ float g_w2t[(size_t)NEXP * DMODEL * HID];       // w2^T [e][d][h] tf32

// ---------------- helpers ----------------
__device__ __forceinline__ unsigned tf32u(float x) {
    unsigned u;
    asm("cvt.rna.tf32.f32 %0, %1;" : "=r"(u) : "f"(x));
    return u;
}
__device__ __forceinline__ float tf32f(float x) { return __uint_as_float(tf32u(x)); }

__device__ __forceinline__ void mma8(float c[4], const unsigned a[4], const unsigned b[2]) {
    asm volatile(
        "mma.sync.aligned.m16n8k8.row.col.f32.tf32.tf32.f32 "
        "{%0,%1,%2,%3}, {%4,%5,%6,%7}, {%8,%9}, {%0,%1,%2,%3};\n"
        : "+f"(c[0]), "+f"(c[1]), "+f"(c[2]), "+f"(c[3])
        : "r"(a[0]), "r"(a[1]), "r"(a[2]), "r"(a[3]), "r"(b[0]), "r"(b[1]));
}
__device__ __forceinline__ void ldsm4(unsigned& r0, unsigned& r1, unsigned& r2, unsigned& r3,
                                      unsigned addr) {
    asm volatile("ldmatrix.sync.aligned.m8n8.x4.shared.b16 {%0,%1,%2,%3}, [%4];\n"
                 : "=r"(r0), "=r"(r1), "=r"(r2), "=r"(r3) : "r"(addr));
}
__device__ __forceinline__ void cp16(unsigned saddr, const void* g) {
    asm volatile("cp.async.cg.shared.global [%0], [%1], 16;\n" :: "r"(saddr), "l"(g));
}
__device__ __forceinline__ void cp16z(unsigned saddr, const void* g, unsigned sz) {
    asm volatile("cp.async.cg.shared.global [%0], [%1], 16, %2;\n" :: "r"(saddr), "l"(g), "r"(sz));
}
__device__ __forceinline__ void cp_commit() { asm volatile("cp.async.commit_group;\n"); }

// ---------------- gating: logits -> top2 gates; zero y; write tf32-rounded x ----------------
__global__ void gating_kernel(const float* __restrict__ x, const float* __restrict__ wg,
                              float* __restrict__ y) {
    int gt = blockIdx.x * blockDim.x + threadIdx.x;
    float4 z4 = make_float4(0.f, 0.f, 0.f, 0.f);
#pragma unroll
    for (int i = 0; i < 8; i++)
        ((float4*)y)[gt + i * 131072] = z4;

    int warp = threadIdx.x >> 5, lane = threadIdx.x & 31;
    int t = blockIdx.x * 8 + warp;
    const float4* xr = (const float4*)(x + (size_t)t * DMODEL);
    float4* xtr = (float4*)(g_xt + (size_t)t * DMODEL);
    float lg[8] = {0.f, 0.f, 0.f, 0.f, 0.f, 0.f, 0.f, 0.f};
#pragma unroll
    for (int j = 0; j < 8; j++) {
        int d4 = lane + 32 * j;
        float4 v = xr[d4];
        // fused round_x: store tf32-rounded copy
        float4 vr;
        vr.x = tf32f(v.x); vr.y = tf32f(v.y); vr.z = tf32f(v.z); vr.w = tf32f(v.w);
        xtr[d4] = vr;
        const float4* wr = (const float4*)(wg + d4 * 4 * NEXP);
        float xv[4] = {v.x, v.y, v.z, v.w};
#pragma unroll
        for (int r = 0; r < 4; r++) {
            float4 w0 = wr[2 * r], w1v = wr[2 * r + 1];
            lg[0] += xv[r] * w0.x;  lg[1] += xv[r] * w0.y;
            lg[2] += xv[r] * w0.z;  lg[3] += xv[r] * w0.w;
            lg[4] += xv[r] * w1v.x; lg[5] += xv[r] * w1v.y;
            lg[6] += xv[r] * w1v.z; lg[7] += xv[r] * w1v.w;
        }
    }
#pragma unroll
    for (int e = 0; e < 8; e++) {
#pragma unroll
        for (int off = 16; off; off >>= 1)
            lg[e] += __shfl_xor_sync(0xffffffffu, lg[e], off);
    }
    if (lane == 0) {
        int e1 = 0; float l1 = lg[0];
        for (int e = 1; e < 8; e++) if (lg[e] > l1) { l1 = lg[e]; e1 = e; }
        int e2 = (e1 == 0) ? 1 : 0; float l2 = lg[e2];
        for (int e = 0; e < 8; e++) if (e != e1 && lg[e] > l2) { l2 = lg[e]; e2 = e; }
        float gg = 1.f / (1.f + expf(l2 - l1));
        g_idx[t * 2] = e1;  g_idx[t * 2 + 1] = e2;
        g_gate[t * 2] = gg; g_gate[t * 2 + 1] = 1.f - gg;
    }
}

// ---------------- GShard slot-major assignment scan ----------------
__global__ void scan_kernel() {
    __shared__ unsigned long long sl[2][1024];
    __shared__ unsigned long long sh[2][1024];
    int tid = threadIdx.x;
    for (int i = tid; i < NEXP * CAP; i += 1024) { g_slot_tok[i] = -1; g_slot_w[i] = 0.f; }

    int ev[8];
    unsigned long long lo = 0ull, hi = 0ull;
#pragma unroll
    for (int j = 0; j < 8; j++) {
        int i = tid * 8 + j;
        int k = i >> 12;
        int t = i & 4095;
        int e = g_idx[t * 2 + k];
        ev[j] = e;
        if (e < 4) lo += 1ull << (16 * e); else hi += 1ull << (16 * (e - 4));
    }
    sl[0][tid] = lo; sh[0][tid] = hi;
    __syncthreads();
    int buf = 0;
    for (int off = 1; off < 1024; off <<= 1) {
        unsigned long long nl = sl[buf][tid], nh = sh[buf][tid];
        if (tid >= off) { nl += sl[buf][tid - off]; nh += sh[buf][tid - off]; }
        sl[buf ^ 1][tid] = nl; sh[buf ^ 1][tid] = nh;
        buf ^= 1;
        __syncthreads();
    }
    unsigned long long exl = sl[buf][tid] - lo;
    unsigned long long exh = sh[buf][tid] - hi;
    int base[8];
#pragma unroll
    for (int e = 0; e < 4; e++) base[e]     = (int)((exl >> (16 * e)) & 0xFFFF);
#pragma unroll
    for (int e = 0; e < 4; e++) base[4 + e] = (int)((exh >> (16 * e)) & 0xFFFF);
#pragma unroll
    for (int j = 0; j < 8; j++) {
        int i = tid * 8 + j;
        int k = i >> 12;
        int t = i & 4095;
        int e = ev[j];
        int loc = base[e]++;
        if (loc < CAP) {
            g_slot_tok[e * CAP + loc] = t;
            g_slot_w[e * CAP + loc]   = g_gate[t * 2 + k];
        }
    }
}

// ---------------- preconvert: transpose + round weights ----------------
// output selected in DEVICE code (host-side __device__ symbol args are invalid).
__global__ void transpose_w_kernel(const float* __restrict__ in, int R, int C, int which) {
    __shared__ float ts[32][33];
    float* out = which ? g_w2t : g_w1t;
    const float* ine = in + (size_t)blockIdx.z * R * C;
    float* oute = out + (size_t)blockIdx.z * R * C;
    int c0 = blockIdx.x * 32, r0 = blockIdx.y * 32;
    int tx = threadIdx.x, ty = threadIdx.y;
#pragma unroll
    for (int j = 0; j < 32; j += 8)
        ts[ty + j][tx] = ine[(size_t)(r0 + ty + j) * C + c0 + tx];
    __syncthreads();
#pragma unroll
    for (int j = 0; j < 32; j += 8)
        oute[(size_t)(c0 + ty + j) * R + r0 + tx] = tf32f(ts[tx][ty + j]);
}

// ---- MMA over one resident K-tile (BK=32), warp tile 64x64, ldmatrix frags ----
__device__ __forceinline__ void tile_mma(unsigned su, unsigned aOff, unsigned bOff,
                                         float acc[4][8][4]) {
#pragma unroll
    for (int ks = 0; ks < 4; ks++) {
        const unsigned ko = ks * 32;   // 8 tf32 = 32 bytes per mma K-step
        unsigned a[4][4], bb[8][2];
#pragma unroll
        for (int mf = 0; mf < 4; mf++)
            ldsm4(a[mf][0], a[mf][1], a[mf][2], a[mf][3],
                  su + aOff + mf * (16 * AS_LD * 4) + ko);
#pragma unroll
        for (int p = 0; p < 4; p++)
            ldsm4(bb[2 * p][0], bb[2 * p][1], bb[2 * p + 1][0], bb[2 * p + 1][1],
                  su + bOff + p * (16 * BS_LDN * 4) + ko);
#pragma unroll
        for (int mf = 0; mf < 4; mf++)
#pragma unroll
            for (int nf = 0; nf < 8; nf++)
                mma8(acc[mf][nf], a[mf], bb[nf]);
    }
}

// ---------------- GEMM1: h = relu(gather(xt) @ w1t^T + b1) ----------------
// grid (CAP/256, HID/128, E), 256 thr, 3-stage cp.async, warp tile 64x64
__global__ __launch_bounds__(256)
void gemm1_kernel(const float* __restrict__ b1) {
    extern __shared__ float smem[];
    __shared__ int tokS[BM];
    const int e  = blockIdx.z;
    const int m0 = blockIdx.x * BM;
    const int n0 = blockIdx.y * BN;
    const int tid = threadIdx.x;
    tokS[tid] = g_slot_tok[e * CAP + m0 + tid];
    __syncthreads();

    const float* w1te = g_w1t + (size_t)e * HID * DMODEL;   // [h][d], n-major
    const int warp = tid >> 5, lane = tid & 31;
    const int wm = (warp >> 1) * 64, wn = (warp & 1) * 64;
    const int g = lane >> 2, tg = lane & 3;

    // cp.async descriptors: A 256 rows x 8 chunks (8/thr), B 128 rows (4/thr)
    const int k16 = tid & 7, rb = tid >> 3;     // rb in [0,32)
    const char* aS[8]; unsigned aZ[8]; unsigned aD[8];
    const char* bS[4]; unsigned bD[4];
    unsigned sbase = (unsigned)__cvta_generic_to_shared(smem);
#pragma unroll
    for (int r = 0; r < 8; r++) {
        int row = rb + 32 * r;
        int tok = tokS[row];
        aS[r] = (const char*)(tok >= 0 ? g_xt + (size_t)tok * DMODEL : g_xt) + k16 * 16;
        aZ[r] = (tok >= 0) ? 16u : 0u;
        aD[r] = sbase + (row * AS_LD + k16 * 4) * 4;
    }
#pragma unroll
    for (int r = 0; r < 4; r++) {
        int row = rb + 32 * r;
        bS[r] = (const char*)(w1te + (size_t)(n0 + row) * DMODEL) + k16 * 16;
        bD[r] = sbase + (AS_SZF + row * BS_LDN + k16 * 4) * 4;
    }

    // ldmatrix per-lane offsets (relative to stage base)
    const int t8 = lane >> 3, lr = lane & 7;
    const unsigned aOff = ((wm + ((t8 & 1) << 3) + lr) * AS_LD + ((t8 >> 1) << 2)) * 4;
    const unsigned bOff = (AS_SZF + (wn + ((t8 >> 1) << 3) + lr) * BS_LDN + ((t8 & 1) << 2)) * 4;

    float acc[4][8][4];
#pragma unroll
    for (int mf = 0; mf < 4; mf++)
#pragma unroll
        for (int nf = 0; nf < 8; nf++)
#pragma unroll
            for (int i = 0; i < 4; i++) acc[mf][nf][i] = 0.f;

#define FILL1(i, s) do { unsigned so_ = (unsigned)(s) * STAGE_B; unsigned ko_ = (unsigned)(i) * 128u; \
    _Pragma("unroll") for (int r_ = 0; r_ < 8; r_++) cp16z(aD[r_] + so_, aS[r_] + ko_, aZ[r_]); \
    _Pragma("unroll") for (int r_ = 0; r_ < 4; r_++) cp16 (bD[r_] + so_, bS[r_] + ko_); \
    cp_commit(); } while (0)

    const int NT = DMODEL / 32;   // 32
    FILL1(0, 0);
    FILL1(1, 1);

    for (int i = 0; i < NT; i++) {
        if (i + 1 < NT) asm volatile("cp.async.wait_group 1;\n");
        else            asm volatile("cp.async.wait_group 0;\n");
        __syncthreads();
        if (i + 2 < NT) FILL1(i + 2, (i + 2) % NSTAGE);
        tile_mma(sbase + (i % NSTAGE) * STAGE_B, aOff, bOff, acc);
    }
#undef FILL1

    float* he = g_h + (size_t)e * CAP * HID;
    const float* b1e = b1 + e * HID;
#pragma unroll
    for (int mf = 0; mf < 4; mf++) {
        int r0 = m0 + wm + mf * 16 + g;
#pragma unroll
        for (int nf = 0; nf < 8; nf++) {
            int c0 = n0 + wn + nf * 8 + 2 * tg;
            float bv0 = b1e[c0], bv1 = b1e[c0 + 1];
            float2 v01 = make_float2(tf32f(fmaxf(acc[mf][nf][0] + bv0, 0.f)),
                                     tf32f(fmaxf(acc[mf][nf][1] + bv1, 0.f)));
            float2 v23 = make_float2(tf32f(fmaxf(acc[mf][nf][2] + bv0, 0.f)),
                                     tf32f(fmaxf(acc[mf][nf][3] + bv1, 0.f)));
            *(float2*)(he + (size_t)r0 * HID + c0)       = v01;
            *(float2*)(he + (size_t)(r0 + 8) * HID + c0) = v23;
        }
    }
}

// ---------------- GEMM2: y += gate * (h @ w2t^T + b2), fused scatter ----------------
// grid (CAP/256, DMODEL/128, E)
__global__ __launch_bounds__(256)
void gemm2_kernel(const float* __restrict__ b2, float* __restrict__ y) {
    extern __shared__ float smem[];
    const int e  = blockIdx.z;
    const int m0 = blockIdx.x * BM;
    const int n0 = blockIdx.y * BN;
    const int tid = threadIdx.x;
    const float* he   = g_h + (size_t)e * CAP * HID;
    const float* w2te = g_w2t + (size_t)e * DMODEL * HID;   // [d][h], n-major
    const int warp = tid >> 5, lane = tid & 31;
    const int wm = (warp >> 1) * 64, wn = (warp & 1) * 64;
    const int g = lane >> 2, tg = lane & 3;

    const int k16 = tid & 7, rb = tid >> 3;
    const char* aS[8]; unsigned aD[8];
    const char* bS[4]; unsigned bD[4];
    unsigned sbase = (unsigned)__cvta_generic_to_shared(smem);
#pragma unroll
    for (int r = 0; r < 8; r++) {
        int row = rb + 32 * r;
        aS[r] = (const char*)(he + (size_t)(m0 + row) * HID) + k16 * 16;
        aD[r] = sbase + (row * AS_LD + k16 * 4) * 4;
    }
#pragma unroll
    for (int r = 0; r < 4; r++) {
        int row = rb + 32 * r;
        bS[r] = (const char*)(w2te + (size_t)(n0 + row) * HID) + k16 * 16;
        bD[r] = sbase + (AS_SZF + row * BS_LDN + k16 * 4) * 4;
    }

    const int t8 = lane >> 3, lr = lane & 7;
    const unsigned aOff = ((wm + ((t8 & 1) << 3) + lr) * AS_LD + ((t8 >> 1) << 2)) * 4;
    const unsigned bOff = (AS_SZF + (wn + ((t8 >> 1) << 3) + lr) * BS_LDN + ((t8 & 1) << 2)) * 4;

    float acc[4][8][4];
#pragma unroll
    for (int mf = 0; mf < 4; mf++)
#pragma unroll
        for (int nf = 0; nf < 8; nf++)
#pragma unroll
            for (int i = 0; i < 4; i++) acc[mf][nf][i] = 0.f;

#define FILL2(i, s) do { unsigned so_ = (unsigned)(s) * STAGE_B; unsigned ko_ = (unsigned)(i) * 128u; \
    _Pragma("unroll") for (int r_ = 0; r_ < 8; r_++) cp16(aD[r_] + so_, aS[r_] + ko_); \
    _Pragma("unroll") for (int r_ = 0; r_ < 4; r_++) cp16(bD[r_] + so_, bS[r_] + ko_); \
    cp_commit(); } while (0)

    const int NT = HID / 32;   // 128
    FILL2(0, 0);
    FILL2(1, 1);

    for (int i = 0; i < NT; i++) {
        if (i + 1 < NT) asm volatile("cp.async.wait_group 1;\n");
        else            asm volatile("cp.async.wait_group 0;\n");
        __syncthreads();
        if (i + 2 < NT) FILL2(i + 2, (i + 2) % NSTAGE);
        tile_mma(sbase + (i % NSTAGE) * STAGE_B, aOff, bOff, acc);
    }
#undef FILL2

    const float* b2e = b2 + e * DMODEL;
#pragma unroll
    for (int mf = 0; mf < 4; mf++) {
        int r0 = m0 + wm + mf * 16 + g;
        int tokA = g_slot_tok[e * CAP + r0];
        float wA = g_slot_w[e * CAP + r0];
        int tokB = g_slot_tok[e * CAP + r0 + 8];
        float wB = g_slot_w[e * CAP + r0 + 8];
#pragma unroll
        for (int nf = 0; nf < 8; nf++) {
            int c0 = n0 + wn + nf * 8 + 2 * tg;
            float bv0 = b2e[c0], bv1 = b2e[c0 + 1];
            if (tokA >= 0) {
                atomicAdd(y + (size_t)tokA * DMODEL + c0,     wA * (acc[mf][nf][0] + bv0));
                atomicAdd(y + (size_t)tokA * DMODEL + c0 + 1, wA * (acc[mf][nf][1] + bv1));
            }
            if (tokB >= 0) {
                atomicAdd(y + (size_t)tokB * DMODEL + c0,     wB * (acc[mf][nf][2] + bv0));
                atomicAdd(y + (size_t)tokB * DMODEL + c0 + 1, wB * (acc[mf][nf][3] + bv1));
            }
        }
    }
}

// ---------------- launcher ----------------
extern "C" void kernel_launch(void* const* d_in, const int* in_sizes, int n_in,
                              void* d_out, int out_size) {
    (void)in_sizes; (void)n_in; (void)out_size;
    const float* x  = (const float*)d_in[0];
    const float* wg = (const float*)d_in[1];
    const float* w1 = (const float*)d_in[2];
    const float* b1 = (const float*)d_in[3];
    const float* w2 = (const float*)d_in[4];
    const float* b2 = (const float*)d_in[5];
    float* y = (float*)d_out;

    cudaFuncSetAttribute(gemm1_kernel, cudaFuncAttributeMaxDynamicSharedMemorySize, SMEM_BYTES);
    cudaFuncSetAttribute(gemm2_kernel, cudaFuncAttributeMaxDynamicSharedMemorySize, SMEM_BYTES);

    gating_kernel<<<TOKENS / 8, 256>>>(x, wg, y);
    scan_kernel<<<1, 1024>>>();
    transpose_w_kernel<<<dim3(HID / 32, DMODEL / 32, NEXP), dim3(32, 8)>>>(w1, DMODEL, HID, 0);
    transpose_w_kernel<<<dim3(DMODEL / 32, HID / 32, NEXP), dim3(32, 8)>>>(w2, HID, DMODEL, 1);
    gemm1_kernel<<<dim3(CAP / BM, HID / BN, NEXP), 256, SMEM_BYTES>>>(b1);
    gemm2_kernel<<<dim3(CAP / BM, DMODEL / BN, NEXP), 256, SMEM_BYTES>>>(b2, y);
}

// round 13
// speedup vs baseline: 1.5381x; 1.5381x over previous
#include <cuda_runtime.h>
#include <cuda_fp16.h>
#include <cstdint>

#define TOKENS 4096
#define DMODEL 1024
#define NEXP   8
#define TOPK   2
#define HID    4096
#define CAP    1024

// ---- fp16 gemm geometry: 128x128 CTA tile, BK=32 halfs, 8 warps of 64x32 ----
#define BM 128
#define BN 128
#define ROWB 80                          // 32 f16 = 64B data + 16B pad per row
#define A_BYTES (BM * ROWB)              // 10240
#define B_BYTES (BN * ROWB)              // 10240
#define STAGE_B (A_BYTES + B_BYTES)      // 20480
#define NSTAGE 4
#define SMEM_BYTES (NSTAGE * STAGE_B)    // 81920 -> 2 CTAs/SM

// ---------------- device scratch (no allocations allowed) ----------------
__device__ int    g_idx[TOKENS * TOPK];
__device__ float  g_gate[TOKENS * TOPK];
__device__ int    g_slot_tok[NEXP * CAP];
__device__ float  g_slot_w[NEXP * CAP];
__device__ __half g_h[(size_t)NEXP * CAP * HID];        // 67 MB hidden (fp16)
__device__ __half g_xh[(size_t)TOKENS * DMODEL];        // 8 MB x (fp16)
__device__ __half g_w1h[(size_t)NEXP * HID * DMODEL];   // 67 MB w1^T [e][h][d] fp16
__device__ __half g_w2h[(size_t)NEXP * DMODEL * HID];   // 67 MB w2^T [e][d][h] fp16

// ---------------- helpers ----------------
__device__ __forceinline__ void mma16(float c[4], const unsigned a[4],
                                      unsigned b0, unsigned b1) {
    asm volatile(
        "mma.sync.aligned.m16n8k16.row.col.f32.f16.f16.f32 "
        "{%0,%1,%2,%3}, {%4,%5,%6,%7}, {%8,%9}, {%0,%1,%2,%3};\n"
        : "+f"(c[0]), "+f"(c[1]), "+f"(c[2]), "+f"(c[3])
        : "r"(a[0]), "r"(a[1]), "r"(a[2]), "r"(a[3]), "r"(b0), "r"(b1));
}
__device__ __forceinline__ void ldsm4(unsigned& r0, unsigned& r1, unsigned& r2, unsigned& r3,
                                      unsigned addr) {
    asm volatile("ldmatrix.sync.aligned.m8n8.x4.shared.b16 {%0,%1,%2,%3}, [%4];\n"
                 : "=r"(r0), "=r"(r1), "=r"(r2), "=r"(r3) : "r"(addr));
}
__device__ __forceinline__ void cp16(unsigned saddr, const void* g) {
    asm volatile("cp.async.cg.shared.global [%0], [%1], 16;\n" :: "r"(saddr), "l"(g));
}
__device__ __forceinline__ void cp16z(unsigned saddr, const void* g, unsigned sz) {
    asm volatile("cp.async.cg.shared.global [%0], [%1], 16, %2;\n" :: "r"(saddr), "l"(g), "r"(sz));
}
__device__ __forceinline__ void cp_commit() { asm volatile("cp.async.commit_group;\n"); }

// ---------------- gating: logits -> top2 gates; zero y; write fp16 x ----------------
__global__ void gating_kernel(const float* __restrict__ x, const float* __restrict__ wg,
                              float* __restrict__ y) {
    int gt = blockIdx.x * blockDim.x + threadIdx.x;
    float4 z4 = make_float4(0.f, 0.f, 0.f, 0.f);
#pragma unroll
    for (int i = 0; i < 8; i++)
        ((float4*)y)[gt + i * 131072] = z4;

    int warp = threadIdx.x >> 5, lane = threadIdx.x & 31;
    int t = blockIdx.x * 8 + warp;
    const float4* xr = (const float4*)(x + (size_t)t * DMODEL);
    __half2* xtr = (__half2*)(g_xh + (size_t)t * DMODEL);
    float lg[8] = {0.f, 0.f, 0.f, 0.f, 0.f, 0.f, 0.f, 0.f};
#pragma unroll
    for (int j = 0; j < 8; j++) {
        int d4 = lane + 32 * j;
        float4 v = xr[d4];
        xtr[d4 * 2]     = __floats2half2_rn(v.x, v.y);
        xtr[d4 * 2 + 1] = __floats2half2_rn(v.z, v.w);
        const float4* wr = (const float4*)(wg + d4 * 4 * NEXP);
        float xv[4] = {v.x, v.y, v.z, v.w};
#pragma unroll
        for (int r = 0; r < 4; r++) {
            float4 w0 = wr[2 * r], w1v = wr[2 * r + 1];
            lg[0] += xv[r] * w0.x;  lg[1] += xv[r] * w0.y;
            lg[2] += xv[r] * w0.z;  lg[3] += xv[r] * w0.w;
            lg[4] += xv[r] * w1v.x; lg[5] += xv[r] * w1v.y;
            lg[6] += xv[r] * w1v.z; lg[7] += xv[r] * w1v.w;
        }
    }
#pragma unroll
    for (int e = 0; e < 8; e++) {
#pragma unroll
        for (int off = 16; off; off >>= 1)
            lg[e] += __shfl_xor_sync(0xffffffffu, lg[e], off);
    }
    if (lane == 0) {
        int e1 = 0; float l1 = lg[0];
        for (int e = 1; e < 8; e++) if (lg[e] > l1) { l1 = lg[e]; e1 = e; }
        int e2 = (e1 == 0) ? 1 : 0; float l2 = lg[e2];
        for (int e = 0; e < 8; e++) if (e != e1 && lg[e] > l2) { l2 = lg[e]; e2 = e; }
        float gg = 1.f / (1.f + expf(l2 - l1));
        g_idx[t * 2] = e1;  g_idx[t * 2 + 1] = e2;
        g_gate[t * 2] = gg; g_gate[t * 2 + 1] = 1.f - gg;
    }
}

// ---------------- GShard slot-major assignment scan ----------------
__global__ void scan_kernel() {
    __shared__ unsigned long long sl[2][1024];
    __shared__ unsigned long long sh[2][1024];
    int tid = threadIdx.x;
    for (int i = tid; i < NEXP * CAP; i += 1024) { g_slot_tok[i] = -1; g_slot_w[i] = 0.f; }

    int ev[8];
    unsigned long long lo = 0ull, hi = 0ull;
#pragma unroll
    for (int j = 0; j < 8; j++) {
        int i = tid * 8 + j;
        int k = i >> 12;
        int t = i & 4095;
        int e = g_idx[t * 2 + k];
        ev[j] = e;
        if (e < 4) lo += 1ull << (16 * e); else hi += 1ull << (16 * (e - 4));
    }
    sl[0][tid] = lo; sh[0][tid] = hi;
    __syncthreads();
    int buf = 0;
    for (int off = 1; off < 1024; off <<= 1) {
        unsigned long long nl = sl[buf][tid], nh = sh[buf][tid];
        if (tid >= off) { nl += sl[buf][tid - off]; nh += sh[buf][tid - off]; }
        sl[buf ^ 1][tid] = nl; sh[buf ^ 1][tid] = nh;
        buf ^= 1;
        __syncthreads();
    }
    unsigned long long exl = sl[buf][tid] - lo;
    unsigned long long exh = sh[buf][tid] - hi;
    int base[8];
#pragma unroll
    for (int e = 0; e < 4; e++) base[e]     = (int)((exl >> (16 * e)) & 0xFFFF);
#pragma unroll
    for (int e = 0; e < 4; e++) base[4 + e] = (int)((exh >> (16 * e)) & 0xFFFF);
#pragma unroll
    for (int j = 0; j < 8; j++) {
        int i = tid * 8 + j;
        int k = i >> 12;
        int t = i & 4095;
        int e = ev[j];
        int loc = base[e]++;
        if (loc < CAP) {
            g_slot_tok[e * CAP + loc] = t;
            g_slot_w[e * CAP + loc]   = g_gate[t * 2 + k];
        }
    }
}

// ---------------- preconvert: transpose + convert weights to fp16 ----------------
// output selected in DEVICE code (host-side __device__ symbol args are invalid).
__global__ void transpose_w_kernel(const float* __restrict__ in, int R, int C, int which) {
    __shared__ float ts[32][33];
    __half* out = which ? g_w2h : g_w1h;
    const float* ine = in + (size_t)blockIdx.z * R * C;
    __half* oute = out + (size_t)blockIdx.z * R * C;
    int c0 = blockIdx.x * 32, r0 = blockIdx.y * 32;
    int tx = threadIdx.x, ty = threadIdx.y;
#pragma unroll
    for (int j = 0; j < 32; j += 8)
        ts[ty + j][tx] = ine[(size_t)(r0 + ty + j) * C + c0 + tx];
    __syncthreads();
#pragma unroll
    for (int j = 0; j < 32; j += 8)
        oute[(size_t)(c0 + ty + j) * R + r0 + tx] = __float2half_rn(ts[tx][ty + j]);
}

// ---- MMA over one resident K-tile (BK=32 halfs, 2 k-steps of 16) ----
__device__ __forceinline__ void tile_mma(unsigned su, unsigned aOff, unsigned bOff,
                                         float acc[4][4][4]) {
#pragma unroll
    for (int ks = 0; ks < 2; ks++) {
        const unsigned ko = ks * 32;   // 16 halfs = 32 bytes per mma K-step
        unsigned a[4][4], b0[4], b1r[4];
#pragma unroll
        for (int mf = 0; mf < 4; mf++)
            ldsm4(a[mf][0], a[mf][1], a[mf][2], a[mf][3],
                  su + aOff + mf * (16 * ROWB) + ko);
        ldsm4(b0[0], b0[1], b0[2], b0[3], su + bOff + ko);
        ldsm4(b1r[0], b1r[1], b1r[2], b1r[3], su + bOff + ko + 16);
#pragma unroll
        for (int mf = 0; mf < 4; mf++)
#pragma unroll
            for (int nf = 0; nf < 4; nf++)
                mma16(acc[mf][nf], a[mf], b0[nf], b1r[nf]);
    }
}

// ---------------- GEMM1: h = relu(gather(xh) @ w1h^T + b1) -> fp16 ----------------
// grid (CAP/128, HID/128, E), 256 thr, 4-stage cp.async depth-3
__global__ __launch_bounds__(256, 2)
void gemm1_kernel(const float* __restrict__ b1) {
    extern __shared__ char smem[];
    __shared__ int tokS[BM];
    const int e  = blockIdx.z;
    const int m0 = blockIdx.x * BM;
    const int n0 = blockIdx.y * BN;
    const int tid = threadIdx.x;
    if (tid < BM) tokS[tid] = g_slot_tok[e * CAP + m0 + tid];
    __syncthreads();

    const __half* w1he = g_w1h + (size_t)e * HID * DMODEL;   // [h][d], d contiguous
    const int warp = tid >> 5, lane = tid & 31;
    const int wm = (warp >> 2) * 64, wn = (warp & 3) * 32;
    const int g = lane >> 2, tg = lane & 3;

    // cp.async: 4 x 16B chunks per 64B row-chunk; rows rb, rb+64 for A and B
    const int k16 = tid & 3, rb = tid >> 2;     // rb in [0,64)
    const char* aS[2]; unsigned aZ[2]; unsigned aD[2];
    const char* bS[2]; unsigned bD[2];
    unsigned sbase = (unsigned)__cvta_generic_to_shared(smem);
#pragma unroll
    for (int r = 0; r < 2; r++) {
        int row = rb + 64 * r;
        int tok = tokS[row];
        aS[r] = (const char*)(g_xh + (size_t)(tok >= 0 ? tok : 0) * DMODEL) + k16 * 16;
        aZ[r] = (tok >= 0) ? 16u : 0u;
        aD[r] = sbase + row * ROWB + k16 * 16;
        bS[r] = (const char*)(w1he + (size_t)(n0 + row) * DMODEL) + k16 * 16;
        bD[r] = sbase + A_BYTES + row * ROWB + k16 * 16;
    }

    // ldmatrix per-lane base offsets (bytes, relative to stage base)
    const unsigned aOff = (wm + (lane & 15)) * ROWB + ((lane >> 4) << 4);
    const unsigned bOff = A_BYTES + (wn + lane) * ROWB;

    float acc[4][4][4];
#pragma unroll
    for (int mf = 0; mf < 4; mf++)
#pragma unroll
        for (int nf = 0; nf < 4; nf++)
#pragma unroll
            for (int i = 0; i < 4; i++) acc[mf][nf][i] = 0.f;

#define FILL1(i, s) do { unsigned so_ = (unsigned)(s) * STAGE_B; unsigned ko_ = (unsigned)(i) * 64u; \
    _Pragma("unroll") for (int r_ = 0; r_ < 2; r_++) { \
        cp16z(aD[r_] + so_, aS[r_] + ko_, aZ[r_]); \
        cp16 (bD[r_] + so_, bS[r_] + ko_); } \
    cp_commit(); } while (0)

    const int NT = DMODEL / 32;   // 32
    FILL1(0, 0); FILL1(1, 1); FILL1(2, 2);

    for (int i = 0; i < NT; i++) {
        if (i < NT - 2)      asm volatile("cp.async.wait_group 2;\n");
        else if (i == NT - 2) asm volatile("cp.async.wait_group 1;\n");
        else                 asm volatile("cp.async.wait_group 0;\n");
        __syncthreads();
        if (i + 3 < NT) FILL1(i + 3, (i + 3) & 3);
        tile_mma(sbase + (i & 3) * STAGE_B, aOff, bOff, acc);
    }
#undef FILL1

    __half* he = g_h + (size_t)e * CAP * HID;
    const float* b1e = b1 + e * HID;
#pragma unroll
    for (int mf = 0; mf < 4; mf++) {
        int r0 = m0 + wm + mf * 16 + g;
#pragma unroll
        for (int nf = 0; nf < 4; nf++) {
            int c0 = n0 + wn + nf * 8 + 2 * tg;
            float bv0 = b1e[c0], bv1 = b1e[c0 + 1];
            *(__half2*)(he + (size_t)r0 * HID + c0) =
                __floats2half2_rn(fmaxf(acc[mf][nf][0] + bv0, 0.f),
                                  fmaxf(acc[mf][nf][1] + bv1, 0.f));
            *(__half2*)(he + (size_t)(r0 + 8) * HID + c0) =
                __floats2half2_rn(fmaxf(acc[mf][nf][2] + bv0, 0.f),
                                  fmaxf(acc[mf][nf][3] + bv1, 0.f));
        }
    }
}

// ---------------- GEMM2: y += gate * (h @ w2h^T + b2), fused scatter ----------------
// grid (CAP/128, DMODEL/128, E)
__global__ __launch_bounds__(256, 2)
void gemm2_kernel(const float* __restrict__ b2, float* __restrict__ y) {
    extern __shared__ char smem[];
    const int e  = blockIdx.z;
    const int m0 = blockIdx.x * BM;
    const int n0 = blockIdx.y * BN;
    const int tid = threadIdx.x;
    const __half* he   = g_h + (size_t)e * CAP * HID;
    const __half* w2he = g_w2h + (size_t)e * DMODEL * HID;   // [d][h], h contiguous
    const int warp = tid >> 5, lane = tid & 31;
    const int wm = (warp >> 2) * 64, wn = (warp & 3) * 32;
    const int g = lane >> 2, tg = lane & 3;

    const int k16 = tid & 3, rb = tid >> 2;
    const char* aS[2]; unsigned aD[2];
    const char* bS[2]; unsigned bD[2];
    unsigned sbase = (unsigned)__cvta_generic_to_shared(smem);
#pragma unroll
    for (int r = 0; r < 2; r++) {
        int row = rb + 64 * r;
        aS[r] = (const char*)(he + (size_t)(m0 + row) * HID) + k16 * 16;
        aD[r] = sbase + row * ROWB + k16 * 16;
        bS[r] = (const char*)(w2he + (size_t)(n0 + row) * HID) + k16 * 16;
        bD[r] = sbase + A_BYTES + row * ROWB + k16 * 16;
    }

    const unsigned aOff = (wm + (lane & 15)) * ROWB + ((lane >> 4) << 4);
    const unsigned bOff = A_BYTES + (wn + lane) * ROWB;

    float acc[4][4][4];
#pragma unroll
    for (int mf = 0; mf < 4; mf++)
#pragma unroll
        for (int nf = 0; nf < 4; nf++)
#pragma unroll
            for (int i = 0; i < 4; i++) acc[mf][nf][i] = 0.f;

#define FILL2(i, s) do { unsigned so_ = (unsigned)(s) * STAGE_B; unsigned ko_ = (unsigned)(i) * 64u; \
    _Pragma("unroll") for (int r_ = 0; r_ < 2; r_++) { \
        cp16(aD[r_] + so_, aS[r_] + ko_); \
        cp16(bD[r_] + so_, bS[r_] + ko_); } \
    cp_commit(); } while (0)

    const int NT = HID / 32;   // 128
    FILL2(0, 0); FILL2(1, 1); FILL2(2, 2);

    for (int i = 0; i < NT; i++) {
        if (i < NT - 2)      asm volatile("cp.async.wait_group 2;\n");
        else if (i == NT - 2) asm volatile("cp.async.wait_group 1;\n");
        else                 asm volatile("cp.async.wait_group 0;\n");
        __syncthreads();
        if (i + 3 < NT) FILL2(i + 3, (i + 3) & 3);
        tile_mma(sbase + (i & 3) * STAGE_B, aOff, bOff, acc);
    }
#undef FILL2

    const float* b2e = b2 + e * DMODEL;
#pragma unroll
    for (int mf = 0; mf < 4; mf++) {
        int r0 = m0 + wm + mf * 16 + g;
        int tokA = g_slot_tok[e * CAP + r0];
        float wA = g_slot_w[e * CAP + r0];
        int tokB = g_slot_tok[e * CAP + r0 + 8];
        float wB = g_slot_w[e * CAP + r0 + 8];
#pragma unroll
        for (int nf = 0; nf < 4; nf++) {
            int c0 = n0 + wn + nf * 8 + 2 * tg;
            float bv0 = b2e[c0], bv1 = b2e[c0 + 1];
            if (tokA >= 0) {
                atomicAdd(y + (size_t)tokA * DMODEL + c0,     wA * (acc[mf][nf][0] + bv0));
                atomicAdd(y + (size_t)tokA * DMODEL + c0 + 1, wA * (acc[mf][nf][1] + bv1));
            }
            if (tokB >= 0) {
                atomicAdd(y + (size_t)tokB * DMODEL + c0,     wB * (acc[mf][nf][2] + bv0));
                atomicAdd(y + (size_t)tokB * DMODEL + c0 + 1, wB * (acc[mf][nf][3] + bv1));
            }
        }
    }
}

// ---------------- launcher ----------------
extern "C" void kernel_launch(void* const* d_in, const int* in_sizes, int n_in,
                              void* d_out, int out_size) {
    (void)in_sizes; (void)n_in; (void)out_size;
    const float* x  = (const float*)d_in[0];
    const float* wg = (const float*)d_in[1];
    const float* w1 = (const float*)d_in[2];
    const float* b1 = (const float*)d_in[3];
    const float* w2 = (const float*)d_in[4];
    const float* b2 = (const float*)d_in[5];
    float* y = (float*)d_out;

    cudaFuncSetAttribute(gemm1_kernel, cudaFuncAttributeMaxDynamicSharedMemorySize, SMEM_BYTES);
    cudaFuncSetAttribute(gemm2_kernel, cudaFuncAttributeMaxDynamicSharedMemorySize, SMEM_BYTES);

    gating_kernel<<<TOKENS / 8, 256>>>(x, wg, y);
    scan_kernel<<<1, 1024>>>();
    transpose_w_kernel<<<dim3(HID / 32, DMODEL / 32, NEXP), dim3(32, 8)>>>(w1, DMODEL, HID, 0);
    transpose_w_kernel<<<dim3(DMODEL / 32, HID / 32, NEXP), dim3(32, 8)>>>(w2, HID, DMODEL, 1);
    gemm1_kernel<<<dim3(CAP / BM, HID / BN, NEXP), 256, SMEM_BYTES>>>(b1);
    gemm2_kernel<<<dim3(CAP / BM, DMODEL / BN, NEXP), 256, SMEM_BYTES>>>(b2, y);
}

// round 15
// speedup vs baseline: 1.6721x; 1.0871x over previous
#include <cuda_runtime.h>
#include <cuda_fp16.h>
#include <cstdint>

#define TOKENS 4096
#define DMODEL 1024
#define NEXP   8
#define TOPK   2
#define HID    4096
#define CAP    1024

// ---- fp16 gemm geometry: 128x128 CTA tile, BK=64 halfs, 8 warps of 64x32 ----
#define BM 128
#define BN 128
#define ROWB 144                         // 64 f16 = 128B data + 16B pad per row
#define A_BYTES (BM * ROWB)              // 18432
#define B_BYTES (BN * ROWB)              // 18432
#define STAGE_B (A_BYTES + B_BYTES)      // 36864
#define NSTAGE 3
#define SMEM_BYTES (NSTAGE * STAGE_B)    // 110592 -> 2 CTAs/SM

// ---------------- device scratch (no allocations allowed) ----------------
__device__ int    g_idx[TOKENS * TOPK];
__device__ float  g_gate[TOKENS * TOPK];
__device__ int    g_slot_tok[NEXP * CAP];
__device__ float  g_slot_w[NEXP * CAP];
__device__ __half g_h[(size_t)NEXP * CAP * HID];        // 67 MB hidden (fp16)
__device__ __half g_xh[(size_t)TOKENS * DMODEL];        // 8 MB x (fp16)
__device__ __half g_w1h[(size_t)NEXP * HID * DMODEL];   // 67 MB w1^T [e][h][d] fp16
__device__ __half g_w2h[(size_t)NEXP * DMODEL * HID];   // 67 MB w2^T [e][d][h] fp16

// ---------------- helpers ----------------
__device__ __forceinline__ void mma16(float c[4], const unsigned a[4],
                                      unsigned b0, unsigned b1) {
    asm volatile(
        "mma.sync.aligned.m16n8k16.row.col.f32.f16.f16.f32 "
        "{%0,%1,%2,%3}, {%4,%5,%6,%7}, {%8,%9}, {%0,%1,%2,%3};\n"
        : "+f"(c[0]), "+f"(c[1]), "+f"(c[2]), "+f"(c[3])
        : "r"(a[0]), "r"(a[1]), "r"(a[2]), "r"(a[3]), "r"(b0), "r"(b1));
}
__device__ __forceinline__ void ldsm4(unsigned& r0, unsigned& r1, unsigned& r2, unsigned& r3,
                                      unsigned addr) {
    asm volatile("ldmatrix.sync.aligned.m8n8.x4.shared.b16 {%0,%1,%2,%3}, [%4];\n"
                 : "=r"(r0), "=r"(r1), "=r"(r2), "=r"(r3) : "r"(addr));
}
__device__ __forceinline__ void cp16(unsigned saddr, const void* g) {
    asm volatile("cp.async.cg.shared.global [%0], [%1], 16;\n" :: "r"(saddr), "l"(g));
}
__device__ __forceinline__ void cp16z(unsigned saddr, const void* g, unsigned sz) {
    asm volatile("cp.async.cg.shared.global [%0], [%1], 16, %2;\n" :: "r"(saddr), "l"(g), "r"(sz));
}
__device__ __forceinline__ void cp_commit() { asm volatile("cp.async.commit_group;\n"); }

// ---------------- gating: logits -> top2 gates; zero y; write fp16 x ----------------
__global__ void gating_kernel(const float* __restrict__ x, const float* __restrict__ wg,
                              float* __restrict__ y) {
    int gt = blockIdx.x * blockDim.x + threadIdx.x;
    float4 z4 = make_float4(0.f, 0.f, 0.f, 0.f);
#pragma unroll
    for (int i = 0; i < 8; i++)
        ((float4*)y)[gt + i * 131072] = z4;

    int warp = threadIdx.x >> 5, lane = threadIdx.x & 31;
    int t = blockIdx.x * 8 + warp;
    const float4* xr = (const float4*)(x + (size_t)t * DMODEL);
    __half2* xtr = (__half2*)(g_xh + (size_t)t * DMODEL);
    float lg[8] = {0.f, 0.f, 0.f, 0.f, 0.f, 0.f, 0.f, 0.f};
#pragma unroll
    for (int j = 0; j < 8; j++) {
        int d4 = lane + 32 * j;
        float4 v = xr[d4];
        xtr[d4 * 2]     = __floats2half2_rn(v.x, v.y);
        xtr[d4 * 2 + 1] = __floats2half2_rn(v.z, v.w);
        const float4* wr = (const float4*)(wg + d4 * 4 * NEXP);
        float xv[4] = {v.x, v.y, v.z, v.w};
#pragma unroll
        for (int r = 0; r < 4; r++) {
            float4 w0 = wr[2 * r], w1v = wr[2 * r + 1];
            lg[0] += xv[r] * w0.x;  lg[1] += xv[r] * w0.y;
            lg[2] += xv[r] * w0.z;  lg[3] += xv[r] * w0.w;
            lg[4] += xv[r] * w1v.x; lg[5] += xv[r] * w1v.y;
            lg[6] += xv[r] * w1v.z; lg[7] += xv[r] * w1v.w;
        }
    }
#pragma unroll
    for (int e = 0; e < 8; e++) {
#pragma unroll
        for (int off = 16; off; off >>= 1)
            lg[e] += __shfl_xor_sync(0xffffffffu, lg[e], off);
    }
    if (lane == 0) {
        int e1 = 0; float l1 = lg[0];
        for (int e = 1; e < 8; e++) if (lg[e] > l1) { l1 = lg[e]; e1 = e; }
        int e2 = (e1 == 0) ? 1 : 0; float l2 = lg[e2];
        for (int e = 0; e < 8; e++) if (e != e1 && lg[e] > l2) { l2 = lg[e]; e2 = e; }
        float gg = 1.f / (1.f + expf(l2 - l1));
        g_idx[t * 2] = e1;  g_idx[t * 2 + 1] = e2;
        g_gate[t * 2] = gg; g_gate[t * 2 + 1] = 1.f - gg;
    }
}

// ---------------- GShard slot-major assignment scan ----------------
__global__ void scan_kernel() {
    __shared__ unsigned long long sl[2][1024];
    __shared__ unsigned long long sh[2][1024];
    int tid = threadIdx.x;
    for (int i = tid; i < NEXP * CAP; i += 1024) { g_slot_tok[i] = -1; g_slot_w[i] = 0.f; }

    int ev[8];
    unsigned long long lo = 0ull, hi = 0ull;
#pragma unroll
    for (int j = 0; j < 8; j++) {
        int i = tid * 8 + j;
        int k = i >> 12;
        int t = i & 4095;
        int e = g_idx[t * 2 + k];
        ev[j] = e;
        if (e < 4) lo += 1ull << (16 * e); else hi += 1ull << (16 * (e - 4));
    }
    sl[0][tid] = lo; sh[0][tid] = hi;
    __syncthreads();
    int buf = 0;
    for (int off = 1; off < 1024; off <<= 1) {
        unsigned long long nl = sl[buf][tid], nh = sh[buf][tid];
        if (tid >= off) { nl += sl[buf][tid - off]; nh += sh[buf][tid - off]; }
        sl[buf ^ 1][tid] = nl; sh[buf ^ 1][tid] = nh;
        buf ^= 1;
        __syncthreads();
    }
    unsigned long long exl = sl[buf][tid] - lo;
    unsigned long long exh = sh[buf][tid] - hi;
    int base[8];
#pragma unroll
    for (int e = 0; e < 4; e++) base[e]     = (int)((exl >> (16 * e)) & 0xFFFF);
#pragma unroll
    for (int e = 0; e < 4; e++) base[4 + e] = (int)((exh >> (16 * e)) & 0xFFFF);
#pragma unroll
    for (int j = 0; j < 8; j++) {
        int i = tid * 8 + j;
        int k = i >> 12;
        int t = i & 4095;
        int e = ev[j];
        int loc = base[e]++;
        if (loc < CAP) {
            g_slot_tok[e * CAP + loc] = t;
            g_slot_w[e * CAP + loc]   = g_gate[t * 2 + k];
        }
    }
}

// ---------------- transpose + convert weights to fp16 (vectorized) ----------------
// in[e]: R x C fp32 row-major -> out[e]: C x R fp16 row-major.
// 64x64 tile, 256 thr: float4 loads, smem half staging, uint4 stores.
// Output selected in DEVICE code (host-side __device__ symbol args are invalid).
__global__ void transpose_w_kernel(const float* __restrict__ in, int R, int C, int which) {
    __shared__ __half hs[64 * 72];          // pitch 72 halfs = 144B (16B aligned)
    __half* out = which ? g_w2h : g_w1h;
    const float* ine = in + (size_t)blockIdx.z * R * C;
    __half* oute = out + (size_t)blockIdx.z * R * C;
    int c0 = blockIdx.x * 64, r0 = blockIdx.y * 64;
    int tid = threadIdx.x;
    int rloc = tid >> 4, c4 = (tid & 15) * 4;
#pragma unroll
    for (int j = 0; j < 4; j++) {
        int r = rloc + 16 * j;
        float4 v = *(const float4*)(ine + (size_t)(r0 + r) * C + c0 + c4);
        hs[(c4 + 0) * 72 + r] = __float2half_rn(v.x);
        hs[(c4 + 1) * 72 + r] = __float2half_rn(v.y);
        hs[(c4 + 2) * 72 + r] = __float2half_rn(v.z);
        hs[(c4 + 3) * 72 + r] = __float2half_rn(v.w);
    }
    __syncthreads();
    int cl = tid >> 3, ch = tid & 7;
#pragma unroll
    for (int j = 0; j < 2; j++) {
        int c = cl + 32 * j;
        uint4 v = *(const uint4*)(hs + c * 72 + ch * 8);
        *(uint4*)(oute + (size_t)(c0 + c) * R + r0 + ch * 8) = v;
    }
}

// ---- MMA over one resident K-tile (BK=64 halfs, 4 k-steps of 16) ----
__device__ __forceinline__ void tile_mma(unsigned su, unsigned aOff, unsigned bOff,
                                         float acc[4][4][4]) {
#pragma unroll
    for (int ks = 0; ks < 4; ks++) {
        const unsigned ko = ks * 32;   // 16 halfs = 32 bytes per mma K-step
        unsigned a[4][4], b0[4], b1r[4];
#pragma unroll
        for (int mf = 0; mf < 4; mf++)
            ldsm4(a[mf][0], a[mf][1], a[mf][2], a[mf][3],
                  su + aOff + mf * (16 * ROWB) + ko);
        ldsm4(b0[0], b0[1], b0[2], b0[3], su + bOff + ko);
        ldsm4(b1r[0], b1r[1], b1r[2], b1r[3], su + bOff + ko + 16);
#pragma unroll
        for (int mf = 0; mf < 4; mf++)
#pragma unroll
            for (int nf = 0; nf < 4; nf++)
                mma16(acc[mf][nf], a[mf], b0[nf], b1r[nf]);
    }
}

// ---------------- GEMM1: h = relu(gather(xh) @ w1h^T + b1) -> fp16 ----------------
// grid (CAP/128, HID/128, E), 256 thr, 3-stage BK=64 cp.async depth-2
__global__ __launch_bounds__(256, 2)
void gemm1_kernel(const float* __restrict__ b1) {
    extern __shared__ char smem[];
    __shared__ int tokS[BM];
    const int e  = blockIdx.z;
    const int m0 = blockIdx.x * BM;
    const int n0 = blockIdx.y * BN;
    const int tid = threadIdx.x;
    if (tid < BM) tokS[tid] = g_slot_tok[e * CAP + m0 + tid];
    __syncthreads();

    const __half* w1he = g_w1h + (size_t)e * HID * DMODEL;   // [h][d], d contiguous
    const int warp = tid >> 5, lane = tid & 31;
    const int wm = (warp >> 2) * 64, wn = (warp & 3) * 32;
    const int g = lane >> 2, tg = lane & 3;

    // cp.async: row = 8 chunks of 16B (+pad); rows rb+32r for A (gather) and B
    const int k8 = tid & 7, rb = tid >> 3;      // chunk 0-7, row base 0-31
    const char* aS[4]; unsigned aZ[4];
    unsigned sbase = (unsigned)__cvta_generic_to_shared(smem);
#pragma unroll
    for (int r = 0; r < 4; r++) {
        int tok = tokS[rb + 32 * r];
        aS[r] = (const char*)(g_xh + (size_t)(tok >= 0 ? tok : 0) * DMODEL) + k8 * 16;
        aZ[r] = (tok >= 0) ? 16u : 0u;
    }
    const char* bB = (const char*)(w1he + (size_t)(n0 + rb) * DMODEL) + k8 * 16;
    const unsigned aD0 = sbase + rb * ROWB + k8 * 16;
    const unsigned bD0 = sbase + A_BYTES + rb * ROWB + k8 * 16;

    // ldmatrix per-lane base offsets (bytes, relative to stage base)
    const unsigned aOff = (wm + (lane & 15)) * ROWB + ((lane >> 4) << 4);
    const unsigned bOff = A_BYTES + (wn + lane) * ROWB;

    float acc[4][4][4];
#pragma unroll
    for (int mf = 0; mf < 4; mf++)
#pragma unroll
        for (int nf = 0; nf < 4; nf++)
#pragma unroll
            for (int i = 0; i < 4; i++) acc[mf][nf][i] = 0.f;

#define FILL1(i, s) do { unsigned so_ = (unsigned)(s) * STAGE_B; unsigned ko_ = (unsigned)(i) * 128u; \
    _Pragma("unroll") for (int r_ = 0; r_ < 4; r_++) { \
        cp16z(aD0 + 4608u * r_ + so_, aS[r_] + ko_, aZ[r_]); \
        cp16 (bD0 + 4608u * r_ + so_, bB + 65536u * r_ + ko_); } \
    cp_commit(); } while (0)

    const int NT = (DMODEL * 2) / 128;   // 16 tiles of BK=64
    FILL1(0, 0); FILL1(1, 1);

    for (int i = 0; i < NT; i++) {
        if (i + 2 < NT) asm volatile("cp.async.wait_group 1;\n");
        else            asm volatile("cp.async.wait_group 0;\n");
        __syncthreads();
        if (i + 2 < NT) FILL1(i + 2, (i + 2) % 3);
        tile_mma(sbase + (i % 3) * STAGE_B, aOff, bOff, acc);
    }
#undef FILL1

    __half* he = g_h + (size_t)e * CAP * HID;
    const float* b1e = b1 + e * HID;
#pragma unroll
    for (int mf = 0; mf < 4; mf++) {
        int r0 = m0 + wm + mf * 16 + g;
#pragma unroll
        for (int nf = 0; nf < 4; nf++) {
            int c0 = n0 + wn + nf * 8 + 2 * tg;
            float bv0 = b1e[c0], bv1 = b1e[c0 + 1];
            *(__half2*)(he + (size_t)r0 * HID + c0) =
                __floats2half2_rn(fmaxf(acc[mf][nf][0] + bv0, 0.f),
                                  fmaxf(acc[mf][nf][1] + bv1, 0.f));
            *(__half2*)(he + (size_t)(r0 + 8) * HID + c0) =
                __floats2half2_rn(fmaxf(acc[mf][nf][2] + bv0, 0.f),
                                  fmaxf(acc[mf][nf][3] + bv1, 0.f));
        }
    }
}

// ---------------- GEMM2: y += gate * (h @ w2h^T + b2), fused scatter ----------------
// grid (CAP/128, DMODEL/128, E)
__global__ __launch_bounds__(256, 2)
void gemm2_kernel(const float* __restrict__ b2, float* __restrict__ y) {
    extern __shared__ char smem[];
    const int e  = blockIdx.z;
    const int m0 = blockIdx.x * BM;
    const int n0 = blockIdx.y * BN;
    const int tid = threadIdx.x;
    const __half* he   = g_h + (size_t)e * CAP * HID;
    const __half* w2he = g_w2h + (size_t)e * DMODEL * HID;   // [d][h], h contiguous
    const int warp = tid >> 5, lane = tid & 31;
    const int wm = (warp >> 2) * 64, wn = (warp & 3) * 32;
    const int g = lane >> 2, tg = lane & 3;

    const int k8 = tid & 7, rb = tid >> 3;
    unsigned sbase = (unsigned)__cvta_generic_to_shared(smem);
    const char* aB = (const char*)(he + (size_t)(m0 + rb) * HID) + k8 * 16;
    const char* bB = (const char*)(w2he + (size_t)(n0 + rb) * HID) + k8 * 16;
    const unsigned aD0 = sbase + rb * ROWB + k8 * 16;
    const unsigned bD0 = sbase + A_BYTES + rb * ROWB + k8 * 16;

    const unsigned aOff = (wm + (lane & 15)) * ROWB + ((lane >> 4) << 4);
    const unsigned bOff = A_BYTES + (wn + lane) * ROWB;

    float acc[4][4][4];
#pragma unroll
    for (int mf = 0; mf < 4; mf++)
#pragma unroll
        for (int nf = 0; nf < 4; nf++)
#pragma unroll
            for (int i = 0; i < 4; i++) acc[mf][nf][i] = 0.f;

#define FILL2(i, s) do { unsigned so_ = (unsigned)(s) * STAGE_B; unsigned ko_ = (unsigned)(i) * 128u; \
    _Pragma("unroll") for (int r_ = 0; r_ < 4; r_++) { \
        cp16(aD0 + 4608u * r_ + so_, aB + 262144u * r_ + ko_); \
        cp16(bD0 + 4608u * r_ + so_, bB + 262144u * r_ + ko_); } \
    cp_commit(); } while (0)

    const int NT = (HID * 2) / 128;   // 64 tiles of BK=64
    FILL2(0, 0); FILL2(1, 1);

    for (int i = 0; i < NT; i++) {
        if (i + 2 < NT) asm volatile("cp.async.wait_group 1;\n");
        else            asm volatile("cp.async.wait_group 0;\n");
        __syncthreads();
        if (i + 2 < NT) FILL2(i + 2, (i + 2) % 3);
        tile_mma(sbase + (i % 3) * STAGE_B, aOff, bOff, acc);
    }
#undef FILL2

    const float* b2e = b2 + e * DMODEL;
#pragma unroll
    for (int mf = 0; mf < 4; mf++) {
        int r0 = m0 + wm + mf * 16 + g;
        int tokA = g_slot_tok[e * CAP + r0];
        float wA = g_slot_w[e * CAP + r0];
        int tokB = g_slot_tok[e * CAP + r0 + 8];
        float wB = g_slot_w[e * CAP + r0 + 8];
#pragma unroll
        for (int nf = 0; nf < 4; nf++) {
            int c0 = n0 + wn + nf * 8 + 2 * tg;
            float bv0 = b2e[c0], bv1 = b2e[c0 + 1];
            if (tokA >= 0) {
                atomicAdd(y + (size_t)tokA * DMODEL + c0,     wA * (acc[mf][nf][0] + bv0));
                atomicAdd(y + (size_t)tokA * DMODEL + c0 + 1, wA * (acc[mf][nf][1] + bv1));
            }
            if (tokB >= 0) {
                atomicAdd(y + (size_t)tokB * DMODEL + c0,     wB * (acc[mf][nf][2] + bv0));
                atomicAdd(y + (size_t)tokB * DMODEL + c0 + 1, wB * (acc[mf][nf][3] + bv1));
            }
        }
    }
}

// ---------------- launcher ----------------
extern "C" void kernel_launch(void* const* d_in, const int* in_sizes, int n_in,
                              void* d_out, int out_size) {
    (void)in_sizes; (void)n_in; (void)out_size;
    const float* x  = (const float*)d_in[0];
    const float* wg = (const float*)d_in[1];
    const float* w1 = (const float*)d_in[2];
    const float* b1 = (const float*)d_in[3];
    const float* w2 = (const float*)d_in[4];
    const float* b2 = (const float*)d_in[5];
    float* y = (float*)d_out;

    cudaFuncSetAttribute(gemm1_kernel, cudaFuncAttributeMaxDynamicSharedMemorySize, SMEM_BYTES);
    cudaFuncSetAttribute(gemm2_kernel, cudaFuncAttributeMaxDynamicSharedMemorySize, SMEM_BYTES);

    gating_kernel<<<TOKENS / 8, 256>>>(x, wg, y);
    scan_kernel<<<1, 1024>>>();
    transpose_w_kernel<<<dim3(HID / 64, DMODEL / 64, NEXP), 256>>>(w1, DMODEL, HID, 0);
    transpose_w_kernel<<<dim3(DMODEL / 64, HID / 64, NEXP), 256>>>(w2, HID, DMODEL, 1);
    gemm1_kernel<<<dim3(CAP / BM, HID / BN, NEXP), 256, SMEM_BYTES>>>(b1);
    gemm2_kernel<<<dim3(CAP / BM, DMODEL / BN, NEXP), 256, SMEM_BYTES>>>(b2, y);
}

// round 16
// speedup vs baseline: 1.7233x; 1.0307x over previous
#include <cuda_runtime.h>
#include <cuda_fp16.h>
#include <cstdint>

#define TOKENS 4096
#define DMODEL 1024
#define NEXP   8
#define TOPK   2
#define HID    4096
#define CAP    1024

// ---- fp16 gemm geometry: 128x128 CTA tile, BK=64 halfs, 8 warps of 64x32 ----
// A tile: 128 m-rows x 64 k (k-contiguous), pitch 144B (9*16 -> ldsm conflict-free)
// B tile: 64 k-rows x 128 n (n-contiguous), pitch 272B (17*16 -> ldsm conflict-free)
#define BM 128
#define BN 128
#define ROWB  144
#define BROWB 272
#define A_BYTES (BM * ROWB)              // 18432
#define B_BYTES (64 * BROWB)             // 17408
#define STAGE_B (A_BYTES + B_BYTES)      // 35840
#define NSTAGE 3
#define SMEM_BYTES (NSTAGE * STAGE_B)    // 107520 -> 2 CTAs/SM

// ---------------- device scratch (no allocations allowed) ----------------
__device__ int    g_idx[TOKENS * TOPK];
__device__ float  g_gate[TOKENS * TOPK];
__device__ int    g_slot_tok[NEXP * CAP];
__device__ float  g_slot_w[NEXP * CAP];
__device__ __half g_h[(size_t)NEXP * CAP * HID];        // 67 MB hidden (fp16)
__device__ __half g_xh[(size_t)TOKENS * DMODEL];        // 8 MB x (fp16)
__device__ __half g_w1h[(size_t)NEXP * DMODEL * HID];   // w1 fp16, ORIGINAL [e][d][h]
__device__ __half g_w2h[(size_t)NEXP * HID * DMODEL];   // w2 fp16, ORIGINAL [e][h][d]

// ---------------- helpers ----------------
__device__ __forceinline__ void mma16(float c[4], const unsigned a[4],
                                      unsigned b0, unsigned b1) {
    asm volatile(
        "mma.sync.aligned.m16n8k16.row.col.f32.f16.f16.f32 "
        "{%0,%1,%2,%3}, {%4,%5,%6,%7}, {%8,%9}, {%0,%1,%2,%3};\n"
        : "+f"(c[0]), "+f"(c[1]), "+f"(c[2]), "+f"(c[3])
        : "r"(a[0]), "r"(a[1]), "r"(a[2]), "r"(a[3]), "r"(b0), "r"(b1));
}
__device__ __forceinline__ void ldsm4(unsigned& r0, unsigned& r1, unsigned& r2, unsigned& r3,
                                      unsigned addr) {
    asm volatile("ldmatrix.sync.aligned.m8n8.x4.shared.b16 {%0,%1,%2,%3}, [%4];\n"
                 : "=r"(r0), "=r"(r1), "=r"(r2), "=r"(r3) : "r"(addr));
}
__device__ __forceinline__ void ldsm4t(unsigned& r0, unsigned& r1, unsigned& r2, unsigned& r3,
                                       unsigned addr) {
    asm volatile("ldmatrix.sync.aligned.m8n8.x4.trans.shared.b16 {%0,%1,%2,%3}, [%4];\n"
                 : "=r"(r0), "=r"(r1), "=r"(r2), "=r"(r3) : "r"(addr));
}
__device__ __forceinline__ void cp16(unsigned saddr, const void* g) {
    asm volatile("cp.async.cg.shared.global [%0], [%1], 16;\n" :: "r"(saddr), "l"(g));
}
__device__ __forceinline__ void cp16z(unsigned saddr, const void* g, unsigned sz) {
    asm volatile("cp.async.cg.shared.global [%0], [%1], 16, %2;\n" :: "r"(saddr), "l"(g), "r"(sz));
}
__device__ __forceinline__ void cp_commit() { asm volatile("cp.async.commit_group;\n"); }

// ---------------- gating: logits -> top2 gates; zero y; write fp16 x ----------------
__global__ void gating_kernel(const float* __restrict__ x, const float* __restrict__ wg,
                              float* __restrict__ y) {
    int gt = blockIdx.x * blockDim.x + threadIdx.x;
    float4 z4 = make_float4(0.f, 0.f, 0.f, 0.f);
#pragma unroll
    for (int i = 0; i < 8; i++)
        ((float4*)y)[gt + i * 131072] = z4;

    int warp = threadIdx.x >> 5, lane = threadIdx.x & 31;
    int t = blockIdx.x * 8 + warp;
    const float4* xr = (const float4*)(x + (size_t)t * DMODEL);
    __half2* xtr = (__half2*)(g_xh + (size_t)t * DMODEL);
    float lg[8] = {0.f, 0.f, 0.f, 0.f, 0.f, 0.f, 0.f, 0.f};
#pragma unroll
    for (int j = 0; j < 8; j++) {
        int d4 = lane + 32 * j;
        float4 v = xr[d4];
        xtr[d4 * 2]     = __floats2half2_rn(v.x, v.y);
        xtr[d4 * 2 + 1] = __floats2half2_rn(v.z, v.w);
        const float4* wr = (const float4*)(wg + d4 * 4 * NEXP);
        float xv[4] = {v.x, v.y, v.z, v.w};
#pragma unroll
        for (int r = 0; r < 4; r++) {
            float4 w0 = wr[2 * r], w1v = wr[2 * r + 1];
            lg[0] += xv[r] * w0.x;  lg[1] += xv[r] * w0.y;
            lg[2] += xv[r] * w0.z;  lg[3] += xv[r] * w0.w;
            lg[4] += xv[r] * w1v.x; lg[5] += xv[r] * w1v.y;
            lg[6] += xv[r] * w1v.z; lg[7] += xv[r] * w1v.w;
        }
    }
#pragma unroll
    for (int e = 0; e < 8; e++) {
#pragma unroll
        for (int off = 16; off; off >>= 1)
            lg[e] += __shfl_xor_sync(0xffffffffu, lg[e], off);
    }
    if (lane == 0) {
        int e1 = 0; float l1 = lg[0];
        for (int e = 1; e < 8; e++) if (lg[e] > l1) { l1 = lg[e]; e1 = e; }
        int e2 = (e1 == 0) ? 1 : 0; float l2 = lg[e2];
        for (int e = 0; e < 8; e++) if (e != e1 && lg[e] > l2) { l2 = lg[e]; e2 = e; }
        float gg = 1.f / (1.f + expf(l2 - l1));
        g_idx[t * 2] = e1;  g_idx[t * 2 + 1] = e2;
        g_gate[t * 2] = gg; g_gate[t * 2 + 1] = 1.f - gg;
    }
}

// ---------------- GShard slot-major assignment scan ----------------
__global__ void scan_kernel() {
    __shared__ unsigned long long sl[2][1024];
    __shared__ unsigned long long sh[2][1024];
    int tid = threadIdx.x;
    for (int i = tid; i < NEXP * CAP; i += 1024) { g_slot_tok[i] = -1; g_slot_w[i] = 0.f; }

    int ev[8];
    unsigned long long lo = 0ull, hi = 0ull;
#pragma unroll
    for (int j = 0; j < 8; j++) {
        int i = tid * 8 + j;
        int k = i >> 12;
        int t = i & 4095;
        int e = g_idx[t * 2 + k];
        ev[j] = e;
        if (e < 4) lo += 1ull << (16 * e); else hi += 1ull << (16 * (e - 4));
    }
    sl[0][tid] = lo; sh[0][tid] = hi;
    __syncthreads();
    int buf = 0;
    for (int off = 1; off < 1024; off <<= 1) {
        unsigned long long nl = sl[buf][tid], nh = sh[buf][tid];
        if (tid >= off) { nl += sl[buf][tid - off]; nh += sh[buf][tid - off]; }
        sl[buf ^ 1][tid] = nl; sh[buf ^ 1][tid] = nh;
        buf ^= 1;
        __syncthreads();
    }
    unsigned long long exl = sl[buf][tid] - lo;
    unsigned long long exh = sh[buf][tid] - hi;
    int base[8];
#pragma unroll
    for (int e = 0; e < 4; e++) base[e]     = (int)((exl >> (16 * e)) & 0xFFFF);
#pragma unroll
    for (int e = 0; e < 4; e++) base[4 + e] = (int)((exh >> (16 * e)) & 0xFFFF);
#pragma unroll
    for (int j = 0; j < 8; j++) {
        int i = tid * 8 + j;
        int k = i >> 12;
        int t = i & 4095;
        int e = ev[j];
        int loc = base[e]++;
        if (loc < CAP) {
            g_slot_tok[e * CAP + loc] = t;
            g_slot_w[e * CAP + loc]   = g_gate[t * 2 + k];
        }
    }
}

// ---------------- streaming fp32->fp16 convert of both weights (layout-preserving) ----------------
#define W1E ((size_t)NEXP * DMODEL * HID)
__global__ void convert_w_kernel(const float* __restrict__ w1, const float* __restrict__ w2) {
    size_t i8 = ((size_t)blockIdx.x * 256 + threadIdx.x) * 8;
    const float* src; __half* dst;
    if (i8 < W1E) { src = w1 + i8; dst = g_w1h + i8; }
    else          { src = w2 + (i8 - W1E); dst = g_w2h + (i8 - W1E); }
    float4 v0 = *(const float4*)src;
    float4 v1 = *(const float4*)(src + 4);
    uint4 u;
    ((__half2*)&u)[0] = __floats2half2_rn(v0.x, v0.y);
    ((__half2*)&u)[1] = __floats2half2_rn(v0.z, v0.w);
    ((__half2*)&u)[2] = __floats2half2_rn(v1.x, v1.y);
    ((__half2*)&u)[3] = __floats2half2_rn(v1.z, v1.w);
    *(uint4*)dst = u;
}

// ---- MMA over one resident K-tile (BK=64 halfs, 4 k-steps of 16) ----
// A non-trans ldsm from m-major tile; B trans ldsm from k-major tile.
__device__ __forceinline__ void tile_mma(unsigned su, unsigned aOff, unsigned bOff,
                                         float acc[4][4][4]) {
#pragma unroll
    for (int ks = 0; ks < 4; ks++) {
        unsigned a[4][4], b0[4], b1r[4];
#pragma unroll
        for (int mf = 0; mf < 4; mf++)
            ldsm4(a[mf][0], a[mf][1], a[mf][2], a[mf][3],
                  su + aOff + mf * (16 * ROWB) + ks * 32);
        ldsm4t(b0[0], b0[1], b0[2], b0[3], su + bOff + ks * (16 * BROWB));
        ldsm4t(b1r[0], b1r[1], b1r[2], b1r[3], su + bOff + ks * (16 * BROWB) + 8 * BROWB);
#pragma unroll
        for (int mf = 0; mf < 4; mf++)
#pragma unroll
            for (int nf = 0; nf < 4; nf++)
                mma16(acc[mf][nf], a[mf], b0[nf], b1r[nf]);
    }
}

// ---------------- GEMM1: h = relu(gather(xh) @ w1 + b1) -> fp16 ----------------
// grid (CAP/128, HID/128, E), 256 thr, 3-stage BK=64 cp.async depth-2
__global__ __launch_bounds__(256, 2)
void gemm1_kernel(const float* __restrict__ b1) {
    extern __shared__ char smem[];
    __shared__ int tokS[BM];
    const int e  = blockIdx.z;
    const int m0 = blockIdx.x * BM;
    const int n0 = blockIdx.y * BN;
    const int tid = threadIdx.x;
    if (tid < BM) tokS[tid] = g_slot_tok[e * CAP + m0 + tid];
    __syncthreads();

    const __half* w1he = g_w1h + (size_t)e * DMODEL * HID;   // [d][h], h contiguous (k-major)
    const int warp = tid >> 5, lane = tid & 31;
    const int wm = (warp >> 2) * 64, wn = (warp & 3) * 32;
    const int g = lane >> 2, tg = lane & 3;

    unsigned sbase = (unsigned)__cvta_generic_to_shared(smem);
    // A: 8 chunks/row of 16B, rows rb+32r (gathered tokens)
    const int k8 = tid & 7, rb = tid >> 3;
    const char* aS[4]; unsigned aZ[4];
#pragma unroll
    for (int r = 0; r < 4; r++) {
        int tok = tokS[rb + 32 * r];
        aS[r] = (const char*)(g_xh + (size_t)(tok >= 0 ? tok : 0) * DMODEL) + k8 * 16;
        aZ[r] = (tok >= 0) ? 16u : 0u;
    }
    const unsigned aD0 = sbase + rb * ROWB + k8 * 16;
    // B: 16 chunks/row of 16B, k-rows (tid>>4)+16r
    const int bc = tid & 15, brw = tid >> 4;
    const char* bB = (const char*)w1he + ((size_t)brw * HID + n0) * 2 + bc * 16;
    const unsigned bD0 = sbase + A_BYTES + brw * BROWB + bc * 16;

    // ldmatrix per-lane base offsets (bytes, relative to stage base)
    const unsigned aOff = (wm + (lane & 15)) * ROWB + ((lane >> 4) << 4);
    const unsigned bOff = A_BYTES + (lane & 7) * BROWB + (wn + ((lane >> 3) << 3)) * 2;

    float acc[4][4][4];
#pragma unroll
    for (int mf = 0; mf < 4; mf++)
#pragma unroll
        for (int nf = 0; nf < 4; nf++)
#pragma unroll
            for (int i = 0; i < 4; i++) acc[mf][nf][i] = 0.f;

#define FILL1(i, s) do { unsigned so_ = (unsigned)(s) * STAGE_B; \
    unsigned koA_ = (unsigned)(i) * 128u; size_t koB_ = (size_t)(i) * (64u * 2u * HID); \
    _Pragma("unroll") for (int r_ = 0; r_ < 4; r_++) { \
        cp16z(aD0 + 4608u * r_ + so_, aS[r_] + koA_, aZ[r_]); \
        cp16 (bD0 + 4352u * r_ + so_, bB + koB_ + (size_t)r_ * (16u * 2u * HID)); } \
    cp_commit(); } while (0)

    const int NT = DMODEL / 64;   // 16
    FILL1(0, 0); FILL1(1, 1);

    for (int i = 0; i < NT; i++) {
        if (i + 2 < NT) asm volatile("cp.async.wait_group 1;\n");
        else            asm volatile("cp.async.wait_group 0;\n");
        __syncthreads();
        if (i + 2 < NT) FILL1(i + 2, (i + 2) % 3);
        tile_mma(sbase + (i % 3) * STAGE_B, aOff, bOff, acc);
    }
#undef FILL1

    __half* he = g_h + (size_t)e * CAP * HID;
    const float* b1e = b1 + e * HID;
#pragma unroll
    for (int mf = 0; mf < 4; mf++) {
        int r0 = m0 + wm + mf * 16 + g;
#pragma unroll
        for (int nf = 0; nf < 4; nf++) {
            int c0 = n0 + wn + nf * 8 + 2 * tg;
            float bv0 = b1e[c0], bv1 = b1e[c0 + 1];
            *(__half2*)(he + (size_t)r0 * HID + c0) =
                __floats2half2_rn(fmaxf(acc[mf][nf][0] + bv0, 0.f),
                                  fmaxf(acc[mf][nf][1] + bv1, 0.f));
            *(__half2*)(he + (size_t)(r0 + 8) * HID + c0) =
                __floats2half2_rn(fmaxf(acc[mf][nf][2] + bv0, 0.f),
                                  fmaxf(acc[mf][nf][3] + bv1, 0.f));
        }
    }
}

// ---------------- GEMM2: y += gate * (h @ w2 + b2), fused scatter ----------------
// grid (CAP/128, DMODEL/128, E)
__global__ __launch_bounds__(256, 2)
void gemm2_kernel(const float* __restrict__ b2, float* __restrict__ y) {
    extern __shared__ char smem[];
    const int e  = blockIdx.z;
    const int m0 = blockIdx.x * BM;
    const int n0 = blockIdx.y * BN;
    const int tid = threadIdx.x;
    const __half* he   = g_h + (size_t)e * CAP * HID;
    const __half* w2he = g_w2h + (size_t)e * HID * DMODEL;   // [h][d], d contiguous (k-major)
    const int warp = tid >> 5, lane = tid & 31;
    const int wm = (warp >> 2) * 64, wn = (warp & 3) * 32;
    const int g = lane >> 2, tg = lane & 3;

    unsigned sbase = (unsigned)__cvta_generic_to_shared(smem);
    const int k8 = tid & 7, rb = tid >> 3;
    const char* aB = (const char*)(he + (size_t)(m0 + rb) * HID) + k8 * 16;
    const unsigned aD0 = sbase + rb * ROWB + k8 * 16;
    const int bc = tid & 15, brw = tid >> 4;
    const char* bB = (const char*)w2he + ((size_t)brw * DMODEL + n0) * 2 + bc * 16;
    const unsigned bD0 = sbase + A_BYTES + brw * BROWB + bc * 16;

    const unsigned aOff = (wm + (lane & 15)) * ROWB + ((lane >> 4) << 4);
    const unsigned bOff = A_BYTES + (lane & 7) * BROWB + (wn + ((lane >> 3) << 3)) * 2;

    float acc[4][4][4];
#pragma unroll
    for (int mf = 0; mf < 4; mf++)
#pragma unroll
        for (int nf = 0; nf < 4; nf++)
#pragma unroll
            for (int i = 0; i < 4; i++) acc[mf][nf][i] = 0.f;

#define FILL2(i, s) do { unsigned so_ = (unsigned)(s) * STAGE_B; \
    unsigned koA_ = (unsigned)(i) * 128u; size_t koB_ = (size_t)(i) * (64u * 2u * DMODEL); \
    _Pragma("unroll") for (int r_ = 0; r_ < 4; r_++) { \
        cp16(aD0 + 4608u * r_ + so_, aB + 262144u * r_ + koA_); \
        cp16(bD0 + 4352u * r_ + so_, bB + koB_ + (size_t)r_ * (16u * 2u * DMODEL)); } \
    cp_commit(); } while (0)

    const int NT = HID / 64;   // 64
    FILL2(0, 0); FILL2(1, 1);

    for (int i = 0; i < NT; i++) {
        if (i + 2 < NT) asm volatile("cp.async.wait_group 1;\n");
        else            asm volatile("cp.async.wait_group 0;\n");
        __syncthreads();
        if (i + 2 < NT) FILL2(i + 2, (i + 2) % 3);
        tile_mma(sbase + (i % 3) * STAGE_B, aOff, bOff, acc);
    }
#undef FILL2

    const float* b2e = b2 + e * DMODEL;
#pragma unroll
    for (int mf = 0; mf < 4; mf++) {
        int r0 = m0 + wm + mf * 16 + g;
        int tokA = g_slot_tok[e * CAP + r0];
        float wA = g_slot_w[e * CAP + r0];
        int tokB = g_slot_tok[e * CAP + r0 + 8];
        float wB = g_slot_w[e * CAP + r0 + 8];
#pragma unroll
        for (int nf = 0; nf < 4; nf++) {
            int c0 = n0 + wn + nf * 8 + 2 * tg;
            float bv0 = b2e[c0], bv1 = b2e[c0 + 1];
            if (tokA >= 0) {
                atomicAdd(y + (size_t)tokA * DMODEL + c0,     wA * (acc[mf][nf][0] + bv0));
                atomicAdd(y + (size_t)tokA * DMODEL + c0 + 1, wA * (acc[mf][nf][1] + bv1));
            }
            if (tokB >= 0) {
                atomicAdd(y + (size_t)tokB * DMODEL + c0,     wB * (acc[mf][nf][2] + bv0));
                atomicAdd(y + (size_t)tokB * DMODEL + c0 + 1, wB * (acc[mf][nf][3] + bv1));
            }
        }
    }
}

// ---------------- launcher ----------------
extern "C" void kernel_launch(void* const* d_in, const int* in_sizes, int n_in,
                              void* d_out, int out_size) {
    (void)in_sizes; (void)n_in; (void)out_size;
    const float* x  = (const float*)d_in[0];
    const float* wg = (const float*)d_in[1];
    const float* w1 = (const float*)d_in[2];
    const float* b1 = (const float*)d_in[3];
    const float* w2 = (const float*)d_in[4];
    const float* b2 = (const float*)d_in[5];
    float* y = (float*)d_out;

    cudaFuncSetAttribute(gemm1_kernel, cudaFuncAttributeMaxDynamicSharedMemorySize, SMEM_BYTES);
    cudaFuncSetAttribute(gemm2_kernel, cudaFuncAttributeMaxDynamicSharedMemorySize, SMEM_BYTES);

    gating_kernel<<<TOKENS / 8, 256>>>(x, wg, y);
    scan_kernel<<<1, 1024>>>();
    convert_w_kernel<<<(unsigned)(2 * W1E / 8 / 256), 256>>>(w1, w2);
    gemm1_kernel<<<dim3(CAP / BM, HID / BN, NEXP), 256, SMEM_BYTES>>>(b1);
    gemm2_kernel<<<dim3(CAP / BM, DMODEL / BN, NEXP), 256, SMEM_BYTES>>>(b2, y);
}

// round 17
// speedup vs baseline: 1.7365x; 1.0076x over previous
#include <cuda_runtime.h>
#include <cuda_fp16.h>
#include <cstdint>

#define TOKENS 4096
#define DMODEL 1024
#define NEXP   8
#define TOPK   2
#define HID    4096
#define CAP    1024

// ---- fp16 gemm geometry: 128x128 CTA tile, BK=64 halfs, 4 warps of 64x64 ----
// A tile: 128 m-rows x 64 k (k-contiguous), pitch 144B (9*16, 144%128=16 -> ldsm conflict-free)
// B tile: 64 k-rows x 128 n (n-contiguous), pitch 272B (17*16, 272%128=16 -> ldsm conflict-free)
#define BM 128
#define BN 128
#define ROWB  144
#define BROWB 272
#define A_BYTES (BM * ROWB)              // 18432
#define B_BYTES (64 * BROWB)             // 17408
#define STAGE_B (A_BYTES + B_BYTES)      // 35840
#define NSTAGE 3
#define SMEM_BYTES (NSTAGE * STAGE_B)    // 107520 -> 2 CTAs/SM (8 warps, 2/SMSP from DIFFERENT CTAs)

// ---------------- device scratch (no allocations allowed) ----------------
__device__ int    g_idx[TOKENS * TOPK];
__device__ float  g_gate[TOKENS * TOPK];
__device__ int    g_slot_tok[NEXP * CAP];
__device__ float  g_slot_w[NEXP * CAP];
__device__ __half g_h[(size_t)NEXP * CAP * HID];        // 67 MB hidden (fp16)
__device__ __half g_xh[(size_t)TOKENS * DMODEL];        // 8 MB x (fp16)
__device__ __half g_w1h[(size_t)NEXP * DMODEL * HID];   // w1 fp16, ORIGINAL [e][d][h]
__device__ __half g_w2h[(size_t)NEXP * HID * DMODEL];   // w2 fp16, ORIGINAL [e][h][d]

// ---------------- helpers ----------------
__device__ __forceinline__ void mma16(float c[4], const unsigned a[4],
                                      unsigned b0, unsigned b1) {
    asm volatile(
        "mma.sync.aligned.m16n8k16.row.col.f32.f16.f16.f32 "
        "{%0,%1,%2,%3}, {%4,%5,%6,%7}, {%8,%9}, {%0,%1,%2,%3};\n"
        : "+f"(c[0]), "+f"(c[1]), "+f"(c[2]), "+f"(c[3])
        : "r"(a[0]), "r"(a[1]), "r"(a[2]), "r"(a[3]), "r"(b0), "r"(b1));
}
__device__ __forceinline__ void ldsm4(unsigned& r0, unsigned& r1, unsigned& r2, unsigned& r3,
                                      unsigned addr) {
    asm volatile("ldmatrix.sync.aligned.m8n8.x4.shared.b16 {%0,%1,%2,%3}, [%4];\n"
                 : "=r"(r0), "=r"(r1), "=r"(r2), "=r"(r3) : "r"(addr));
}
__device__ __forceinline__ void ldsm4t(unsigned& r0, unsigned& r1, unsigned& r2, unsigned& r3,
                                       unsigned addr) {
    asm volatile("ldmatrix.sync.aligned.m8n8.x4.trans.shared.b16 {%0,%1,%2,%3}, [%4];\n"
                 : "=r"(r0), "=r"(r1), "=r"(r2), "=r"(r3) : "r"(addr));
}
__device__ __forceinline__ void cp16(unsigned saddr, const void* g) {
    asm volatile("cp.async.cg.shared.global [%0], [%1], 16;\n" :: "r"(saddr), "l"(g));
}
__device__ __forceinline__ void cp16z(unsigned saddr, const void* g, unsigned sz) {
    asm volatile("cp.async.cg.shared.global [%0], [%1], 16, %2;\n" :: "r"(saddr), "l"(g), "r"(sz));
}
__device__ __forceinline__ void cp_commit() { asm volatile("cp.async.commit_group;\n"); }

// ---------------- gating: logits -> top2 gates; zero y; write fp16 x ----------------
__global__ void gating_kernel(const float* __restrict__ x, const float* __restrict__ wg,
                              float* __restrict__ y) {
    int gt = blockIdx.x * blockDim.x + threadIdx.x;
    float4 z4 = make_float4(0.f, 0.f, 0.f, 0.f);
#pragma unroll
    for (int i = 0; i < 8; i++)
        ((float4*)y)[gt + i * 131072] = z4;

    int warp = threadIdx.x >> 5, lane = threadIdx.x & 31;
    int t = blockIdx.x * 8 + warp;
    const float4* xr = (const float4*)(x + (size_t)t * DMODEL);
    __half2* xtr = (__half2*)(g_xh + (size_t)t * DMODEL);
    float lg[8] = {0.f, 0.f, 0.f, 0.f, 0.f, 0.f, 0.f, 0.f};
#pragma unroll
    for (int j = 0; j < 8; j++) {
        int d4 = lane + 32 * j;
        float4 v = xr[d4];
        xtr[d4 * 2]     = __floats2half2_rn(v.x, v.y);
        xtr[d4 * 2 + 1] = __floats2half2_rn(v.z, v.w);
        const float4* wr = (const float4*)(wg + d4 * 4 * NEXP);
        float xv[4] = {v.x, v.y, v.z, v.w};
#pragma unroll
        for (int r = 0; r < 4; r++) {
            float4 w0 = wr[2 * r], w1v = wr[2 * r + 1];
            lg[0] += xv[r] * w0.x;  lg[1] += xv[r] * w0.y;
            lg[2] += xv[r] * w0.z;  lg[3] += xv[r] * w0.w;
            lg[4] += xv[r] * w1v.x; lg[5] += xv[r] * w1v.y;
            lg[6] += xv[r] * w1v.z; lg[7] += xv[r] * w1v.w;
        }
    }
#pragma unroll
    for (int e = 0; e < 8; e++) {
#pragma unroll
        for (int off = 16; off; off >>= 1)
            lg[e] += __shfl_xor_sync(0xffffffffu, lg[e], off);
    }
    if (lane == 0) {
        int e1 = 0; float l1 = lg[0];
        for (int e = 1; e < 8; e++) if (lg[e] > l1) { l1 = lg[e]; e1 = e; }
        int e2 = (e1 == 0) ? 1 : 0; float l2 = lg[e2];
        for (int e = 0; e < 8; e++) if (e != e1 && lg[e] > l2) { l2 = lg[e]; e2 = e; }
        float gg = 1.f / (1.f + expf(l2 - l1));
        g_idx[t * 2] = e1;  g_idx[t * 2 + 1] = e2;
        g_gate[t * 2] = gg; g_gate[t * 2 + 1] = 1.f - gg;
    }
}

// ---------------- GShard slot-major assignment scan ----------------
__global__ void scan_kernel() {
    __shared__ unsigned long long sl[2][1024];
    __shared__ unsigned long long sh[2][1024];
    int tid = threadIdx.x;
    for (int i = tid; i < NEXP * CAP; i += 1024) { g_slot_tok[i] = -1; g_slot_w[i] = 0.f; }

    int ev[8];
    unsigned long long lo = 0ull, hi = 0ull;
#pragma unroll
    for (int j = 0; j < 8; j++) {
        int i = tid * 8 + j;
        int k = i >> 12;
        int t = i & 4095;
        int e = g_idx[t * 2 + k];
        ev[j] = e;
        if (e < 4) lo += 1ull << (16 * e); else hi += 1ull << (16 * (e - 4));
    }
    sl[0][tid] = lo; sh[0][tid] = hi;
    __syncthreads();
    int buf = 0;
    for (int off = 1; off < 1024; off <<= 1) {
        unsigned long long nl = sl[buf][tid], nh = sh[buf][tid];
        if (tid >= off) { nl += sl[buf][tid - off]; nh += sh[buf][tid - off]; }
        sl[buf ^ 1][tid] = nl; sh[buf ^ 1][tid] = nh;
        buf ^= 1;
        __syncthreads();
    }
    unsigned long long exl = sl[buf][tid] - lo;
    unsigned long long exh = sh[buf][tid] - hi;
    int base[8];
#pragma unroll
    for (int e = 0; e < 4; e++) base[e]     = (int)((exl >> (16 * e)) & 0xFFFF);
#pragma unroll
    for (int e = 0; e < 4; e++) base[4 + e] = (int)((exh >> (16 * e)) & 0xFFFF);
#pragma unroll
    for (int j = 0; j < 8; j++) {
        int i = tid * 8 + j;
        int k = i >> 12;
        int t = i & 4095;
        int e = ev[j];
        int loc = base[e]++;
        if (loc < CAP) {
            g_slot_tok[e * CAP + loc] = t;
            g_slot_w[e * CAP + loc]   = g_gate[t * 2 + k];
        }
    }
}

// ---------------- streaming fp32->fp16 convert of both weights (layout-preserving) ----------------
#define W1E ((size_t)NEXP * DMODEL * HID)
__global__ void convert_w_kernel(const float* __restrict__ w1, const float* __restrict__ w2) {
    size_t i8 = ((size_t)blockIdx.x * 256 + threadIdx.x) * 8;
    const float* src; __half* dst;
    if (i8 < W1E) { src = w1 + i8; dst = g_w1h + i8; }
    else          { src = w2 + (i8 - W1E); dst = g_w2h + (i8 - W1E); }
    float4 v0 = *(const float4*)src;
    float4 v1 = *(const float4*)(src + 4);
    uint4 u;
    ((__half2*)&u)[0] = __floats2half2_rn(v0.x, v0.y);
    ((__half2*)&u)[1] = __floats2half2_rn(v0.z, v0.w);
    ((__half2*)&u)[2] = __floats2half2_rn(v1.x, v1.y);
    ((__half2*)&u)[3] = __floats2half2_rn(v1.z, v1.w);
    *(uint4*)dst = u;
}

// ---- MMA over one resident K-tile (BK=64, 4 k-steps of 16), warp tile 64x64 ----
// A non-trans ldsm from m-major tile; B trans ldsm from k-major tile.
__device__ __forceinline__ void tile_mma(unsigned su, unsigned aOff, unsigned bOff,
                                         float acc[4][8][4]) {
#pragma unroll
    for (int ks = 0; ks < 4; ks++) {
        unsigned a[4][4], b0a[4], b1a[4], b0b[4], b1b[4];
#pragma unroll
        for (int mf = 0; mf < 4; mf++)
            ldsm4(a[mf][0], a[mf][1], a[mf][2], a[mf][3],
                  su + aOff + mf * (16 * ROWB) + ks * 32);
        ldsm4t(b0a[0], b0a[1], b0a[2], b0a[3], su + bOff + ks * (16 * BROWB));
        ldsm4t(b1a[0], b1a[1], b1a[2], b1a[3], su + bOff + ks * (16 * BROWB) + 8 * BROWB);
        ldsm4t(b0b[0], b0b[1], b0b[2], b0b[3], su + bOff + ks * (16 * BROWB) + 64);
        ldsm4t(b1b[0], b1b[1], b1b[2], b1b[3], su + bOff + ks * (16 * BROWB) + 8 * BROWB + 64);
#pragma unroll
        for (int mf = 0; mf < 4; mf++) {
#pragma unroll
            for (int nf = 0; nf < 4; nf++)
                mma16(acc[mf][nf], a[mf], b0a[nf], b1a[nf]);
#pragma unroll
            for (int nf = 0; nf < 4; nf++)
                mma16(acc[mf][nf + 4], a[mf], b0b[nf], b1b[nf]);
        }
    }
}

// ---------------- GEMM1: h = relu(gather(xh) @ w1 + b1) -> fp16 ----------------
// grid (CAP/128, HID/128, E), 128 thr (4 warps of 64x64), 3-stage BK=64 cp.async depth-2
__global__ __launch_bounds__(128, 2)
void gemm1_kernel(const float* __restrict__ b1) {
    extern __shared__ char smem[];
    __shared__ int tokS[BM];
    const int e  = blockIdx.z;
    const int m0 = blockIdx.x * BM;
    const int n0 = blockIdx.y * BN;
    const int tid = threadIdx.x;
    tokS[tid] = g_slot_tok[e * CAP + m0 + tid];
    __syncthreads();

    const __half* w1he = g_w1h + (size_t)e * DMODEL * HID;   // [d][h], h contiguous (k-major)
    const int warp = tid >> 5, lane = tid & 31;
    const int wm = (warp >> 1) * 64, wn = (warp & 1) * 64;
    const int g = lane >> 2, tg = lane & 3;

    unsigned sbase = (unsigned)__cvta_generic_to_shared(smem);
    // A: 8 chunks/row of 16B; rows rbase+16r (gathered tokens), 8 per thread
    const int k8 = tid & 7, rbase = tid >> 3;     // rbase in [0,16)
    const char* aS[8]; unsigned aZ[8];
#pragma unroll
    for (int r = 0; r < 8; r++) {
        int tok = tokS[rbase + 16 * r];
        aS[r] = (const char*)(g_xh + (size_t)(tok >= 0 ? tok : 0) * DMODEL) + k8 * 16;
        aZ[r] = (tok >= 0) ? 16u : 0u;
    }
    const unsigned aD0 = sbase + rbase * ROWB + k8 * 16;
    // B: 16 chunks/row of 16B; k-rows brw+8r, 8 per thread
    const int bc = tid & 15, brw = tid >> 4;      // brw in [0,8)
    const char* bB = (const char*)w1he + ((size_t)brw * HID + n0) * 2 + bc * 16;
    const unsigned bD0 = sbase + A_BYTES + brw * BROWB + bc * 16;

    // ldmatrix per-lane base offsets (bytes, relative to stage base)
    const unsigned aOff = (wm + (lane & 15)) * ROWB + ((lane >> 4) << 4);
    const unsigned bOff = A_BYTES + (lane & 7) * BROWB + (wn + ((lane >> 3) << 3)) * 2;

    float acc[4][8][4];
#pragma unroll
    for (int mf = 0; mf < 4; mf++)
#pragma unroll
        for (int nf = 0; nf < 8; nf++)
#pragma unroll
            for (int i = 0; i < 4; i++) acc[mf][nf][i] = 0.f;

#define FILL1(i, s) do { unsigned so_ = (unsigned)(s) * STAGE_B; \
    unsigned koA_ = (unsigned)(i) * 128u; size_t koB_ = (size_t)(i) * (64u * 2u * HID); \
    _Pragma("unroll") for (int r_ = 0; r_ < 8; r_++) \
        cp16z(aD0 + 2304u * r_ + so_, aS[r_] + koA_, aZ[r_]); \
    _Pragma("unroll") for (int r_ = 0; r_ < 8; r_++) \
        cp16 (bD0 + 2176u * r_ + so_, bB + koB_ + (size_t)r_ * (8u * 2u * HID)); \
    cp_commit(); } while (0)

    const int NT = DMODEL / 64;   // 16
    FILL1(0, 0); FILL1(1, 1);

#pragma unroll 1
    for (int i = 0; i < NT; i++) {
        if (i + 2 < NT) asm volatile("cp.async.wait_group 1;\n");
        else            asm volatile("cp.async.wait_group 0;\n");
        __syncthreads();
        if (i + 2 < NT) FILL1(i + 2, (i + 2) % 3);
        tile_mma(sbase + (i % 3) * STAGE_B, aOff, bOff, acc);
    }
#undef FILL1

    __half* he = g_h + (size_t)e * CAP * HID;
    const float* b1e = b1 + e * HID;
#pragma unroll
    for (int mf = 0; mf < 4; mf++) {
        int r0 = m0 + wm + mf * 16 + g;
#pragma unroll
        for (int nf = 0; nf < 8; nf++) {
            int c0 = n0 + wn + nf * 8 + 2 * tg;
            float bv0 = b1e[c0], bv1 = b1e[c0 + 1];
            *(__half2*)(he + (size_t)r0 * HID + c0) =
                __floats2half2_rn(fmaxf(acc[mf][nf][0] + bv0, 0.f),
                                  fmaxf(acc[mf][nf][1] + bv1, 0.f));
            *(__half2*)(he + (size_t)(r0 + 8) * HID + c0) =
                __floats2half2_rn(fmaxf(acc[mf][nf][2] + bv0, 0.f),
                                  fmaxf(acc[mf][nf][3] + bv1, 0.f));
        }
    }
}

// ---------------- GEMM2: y += gate * (h @ w2 + b2), fused scatter ----------------
// grid (CAP/128, DMODEL/128, E), 128 thr (4 warps of 64x64)
__global__ __launch_bounds__(128, 2)
void gemm2_kernel(const float* __restrict__ b2, float* __restrict__ y) {
    extern __shared__ char smem[];
    const int e  = blockIdx.z;
    const int m0 = blockIdx.x * BM;
    const int n0 = blockIdx.y * BN;
    const int tid = threadIdx.x;
    const __half* he   = g_h + (size_t)e * CAP * HID;
    const __half* w2he = g_w2h + (size_t)e * HID * DMODEL;   // [h][d], d contiguous (k-major)
    const int warp = tid >> 5, lane = tid & 31;
    const int wm = (warp >> 1) * 64, wn = (warp & 1) * 64;
    const int g = lane >> 2, tg = lane & 3;

    unsigned sbase = (unsigned)__cvta_generic_to_shared(smem);
    const int k8 = tid & 7, rbase = tid >> 3;
    const char* aB = (const char*)(he + (size_t)(m0 + rbase) * HID) + k8 * 16;
    const unsigned aD0 = sbase + rbase * ROWB + k8 * 16;
    const int bc = tid & 15, brw = tid >> 4;
    const char* bB = (const char*)w2he + ((size_t)brw * DMODEL + n0) * 2 + bc * 16;
    const unsigned bD0 = sbase + A_BYTES + brw * BROWB + bc * 16;

    const unsigned aOff = (wm + (lane & 15)) * ROWB + ((lane >> 4) << 4);
    const unsigned bOff = A_BYTES + (lane & 7) * BROWB + (wn + ((lane >> 3) << 3)) * 2;

    float acc[4][8][4];
#pragma unroll
    for (int mf = 0; mf < 4; mf++)
#pragma unroll
        for (int nf = 0; nf < 8; nf++)
#pragma unroll
            for (int i = 0; i < 4; i++) acc[mf][nf][i] = 0.f;

#define FILL2(i, s) do { unsigned so_ = (unsigned)(s) * STAGE_B; \
    unsigned koA_ = (unsigned)(i) * 128u; size_t koB_ = (size_t)(i) * (64u * 2u * DMODEL); \
    _Pragma("unroll") for (int r_ = 0; r_ < 8; r_++) \
        cp16(aD0 + 2304u * r_ + so_, aB + (size_t)r_ * (16u * 2u * HID) + koA_); \
    _Pragma("unroll") for (int r_ = 0; r_ < 8; r_++) \
        cp16(bD0 + 2176u * r_ + so_, bB + koB_ + (size_t)r_ * (8u * 2u * DMODEL)); \
    cp_commit(); } while (0)

    const int NT = HID / 64;   // 64
    FILL2(0, 0); FILL2(1, 1);

#pragma unroll 1
    for (int i = 0; i < NT; i++) {
        if (i + 2 < NT) asm volatile("cp.async.wait_group 1;\n");
        else            asm volatile("cp.async.wait_group 0;\n");
        __syncthreads();
        if (i + 2 < NT) FILL2(i + 2, (i + 2) % 3);
        tile_mma(sbase + (i % 3) * STAGE_B, aOff, bOff, acc);
    }
#undef FILL2

    const float* b2e = b2 + e * DMODEL;
#pragma unroll
    for (int mf = 0; mf < 4; mf++) {
        int r0 = m0 + wm + mf * 16 + g;
        int tokA = g_slot_tok[e * CAP + r0];
        float wA = g_slot_w[e * CAP + r0];
        int tokB = g_slot_tok[e * CAP + r0 + 8];
        float wB = g_slot_w[e * CAP + r0 + 8];
#pragma unroll
        for (int nf = 0; nf < 8; nf++) {
            int c0 = n0 + wn + nf * 8 + 2 * tg;
            float bv0 = b2e[c0], bv1 = b2e[c0 + 1];
            if (tokA >= 0) {
                atomicAdd(y + (size_t)tokA * DMODEL + c0,     wA * (acc[mf][nf][0] + bv0));
                atomicAdd(y + (size_t)tokA * DMODEL + c0 + 1, wA * (acc[mf][nf][1] + bv1));
            }
            if (tokB >= 0) {
                atomicAdd(y + (size_t)tokB * DMODEL + c0,     wB * (acc[mf][nf][2] + bv0));
                atomicAdd(y + (size_t)tokB * DMODEL + c0 + 1, wB * (acc[mf][nf][3] + bv1));
            }
        }
    }
}

// ---------------- launcher ----------------
extern "C" void kernel_launch(void* const* d_in, const int* in_sizes, int n_in,
                              void* d_out, int out_size) {
    (void)in_sizes; (void)n_in; (void)out_size;
    const float* x  = (const float*)d_in[0];
    const float* wg = (const float*)d_in[1];
    const float* w1 = (const float*)d_in[2];
    const float* b1 = (const float*)d_in[3];
    const float* w2 = (const float*)d_in[4];
    const float* b2 = (const float*)d_in[5];
    float* y = (float*)d_out;

    cudaFuncSetAttribute(gemm1_kernel, cudaFuncAttributeMaxDynamicSharedMemorySize, SMEM_BYTES);
    cudaFuncSetAttribute(gemm2_kernel, cudaFuncAttributeMaxDynamicSharedMemorySize, SMEM_BYTES);

    gating_kernel<<<TOKENS / 8, 256>>>(x, wg, y);
    scan_kernel<<<1, 1024>>>();
    convert_w_kernel<<<(unsigned)(2 * W1E / 8 / 256), 256>>>(w1, w2);
    gemm1_kernel<<<dim3(CAP / BM, HID / BN, NEXP), 128, SMEM_BYTES>>>(b1);
    gemm2_kernel<<<dim3(CAP / BM, DMODEL / BN, NEXP), 128, SMEM_BYTES>>>(b2, y);
}